// round 14
// baseline (speedup 1.0000x reference)
#include <cuda_runtime.h>
#include <cuda_bf16.h>
#include <cstdint>
#include <cstddef>

#define D 128
#define MAXN 50176
#define MAXE 1048576

// ================= global scratch (no allocations allowed) =================
__device__ __align__(16) float g_xh  [(size_t)MAXN * D];           // fp32 xh (gather source)
__device__ __align__(16) __nv_bfloat16 g_xhh[(size_t)MAXN * D];    // xh hi
__device__ __align__(16) __nv_bfloat16 g_xhl[(size_t)MAXN * D];    // xh lo
__device__ __align__(16) __nv_bfloat16 g_t1h[(size_t)MAXN * D];    // Tx1 hi
__device__ __align__(16) __nv_bfloat16 g_t1l[(size_t)MAXN * D];    // Tx1 lo
__device__ __align__(16) __nv_bfloat16 g_mnh[(size_t)MAXN * D];    // mean hi
__device__ __align__(16) __nv_bfloat16 g_mnl[(size_t)MAXN * D];    // mean lo
__device__ __align__(16) __nv_bfloat16 g_o12h[(size_t)MAXN * D];
__device__ __align__(16) __nv_bfloat16 g_o12l[(size_t)MAXN * D];
__device__ __align__(16) __nv_bfloat16 g_wh[6][D * D];
__device__ __align__(16) __nv_bfloat16 g_wl[6][D * D];
__device__ float g_deg [MAXN];
__device__ float g_dis [MAXN];
__device__ int   g_hist[MAXN];
__device__ int   g_base[MAXN];
__device__ int   g_cursor[MAXN];
__device__ __align__(16) int2 g_epack[MAXE];

enum { WP = 0, WC0, WC1, WREL, WROOT, WLIN };

// ================= helpers =================
__device__ __forceinline__ uint32_t smem_u32(const void* p) {
    return (uint32_t)__cvta_generic_to_shared(p);
}
__device__ __forceinline__ uint32_t sw_off(int row, int c16) {
    return (uint32_t)(row * 256 + ((c16 ^ (row & 7)) << 4));
}
__device__ __forceinline__ void ldx4(uint32_t r[4], uint32_t a) {
    asm volatile("ldmatrix.sync.aligned.m8n8.x4.shared.b16 {%0,%1,%2,%3}, [%4];"
                 : "=r"(r[0]), "=r"(r[1]), "=r"(r[2]), "=r"(r[3]) : "r"(a));
}
__device__ __forceinline__ void mma16816(float c[4], const uint32_t a[4],
                                         uint32_t b0, uint32_t b1) {
    asm volatile("mma.sync.aligned.m16n8k16.row.col.f32.bf16.bf16.f32 "
                 "{%0,%1,%2,%3}, {%4,%5,%6,%7}, {%8,%9}, {%0,%1,%2,%3};"
                 : "+f"(c[0]), "+f"(c[1]), "+f"(c[2]), "+f"(c[3])
                 : "r"(a[0]), "r"(a[1]), "r"(a[2]), "r"(a[3]), "r"(b0), "r"(b1));
}
__device__ __forceinline__ uint32_t pk(__nv_bfloat16 a, __nv_bfloat16 b) {
    return (uint32_t)__bfloat16_as_ushort(a) | ((uint32_t)__bfloat16_as_ushort(b) << 16);
}
__device__ __forceinline__ void cpa16(uint32_t dst, const void* src) {
    asm volatile("cp.async.cg.shared.global [%0], [%1], 16;" :: "r"(dst), "l"(src));
}
#define CPA_COMMIT() asm volatile("cp.async.commit_group;" ::: "memory")
#define CPA_WAIT0()  asm volatile("cp.async.wait_group 0;" ::: "memory")

template<int ROWS>
__device__ __forceinline__ void load_async(const __nv_bfloat16* __restrict__ src, int m0,
                                           uint32_t dst, int tid) {
#pragma unroll
    for (int t = 0; t < ROWS * 16 / 256; t++) {
        int idx = tid + t * 256;
        int row = idx >> 4, c16 = idx & 15;
        cpa16(dst + sw_off(row, c16), src + (size_t)(m0 + row) * D + c16 * 8);
    }
}

// load 64x128 fp32 tile (row guard), split hi/lo swizzled; also copy rows to 'his'
__device__ __forceinline__ void load_split64_copy(const float* __restrict__ src, int m0, int n,
                                                  char* ah, char* al,
                                                  float* __restrict__ his, int tid) {
#pragma unroll
    for (int t = 0; t < 4; t++) {
        int idx = tid + t * 256;
        int row = idx >> 4, c16 = idx & 15;
        int gr = m0 + row;
        float4 v0 = make_float4(0.f, 0.f, 0.f, 0.f), v1 = v0;
        if (gr < n) {
            const float* p = src + (size_t)gr * D + c16 * 8;
            v0 = *(const float4*)p;
            v1 = *(const float4*)(p + 4);
            float* q = his + (size_t)gr * D + c16 * 8;
            *(float4*)q = v0;
            *(float4*)(q + 4) = v1;
        }
        float f[8] = {v0.x, v0.y, v0.z, v0.w, v1.x, v1.y, v1.z, v1.w};
        __nv_bfloat16 h[8], l[8];
#pragma unroll
        for (int q = 0; q < 8; q++) {
            h[q] = __float2bfloat16(f[q]);
            l[q] = __float2bfloat16(f[q] - __bfloat162float(h[q]));
        }
        uint32_t off = sw_off(row, c16);
        *(uint4*)(ah + off) = make_uint4(pk(h[0],h[1]), pk(h[2],h[3]), pk(h[4],h[5]), pk(h[6],h[7]));
        *(uint4*)(al + off) = make_uint4(pk(l[0],l[1]), pk(l[2],l[3]), pk(l[4],l[5]), pk(l[6],l[7]));
    }
}

// warp tile 32(m) x 32(n), K=128; acc += Ah*Bh + Ah*Bl + Al*Bh
__device__ __forceinline__ void warp_phase32(
    uint32_t aH, uint32_t aL, uint32_t bH, uint32_t bL,
    int m_base, int n_base, int lane, float acc[2][4][4])
{
    int r = lane & 15, chs = lane >> 4;
#pragma unroll
    for (int kk = 0; kk < 8; kk++) {
        int c = 2 * kk + chs;
        uint32_t ah[2][4], al[2][4], bh[2][4], bl[2][4];
#pragma unroll
        for (int mt = 0; mt < 2; mt++) {
            uint32_t off = sw_off(m_base + mt * 16 + r, c);
            ldx4(ah[mt], aH + off);
            ldx4(al[mt], aL + off);
        }
#pragma unroll
        for (int g = 0; g < 2; g++) {
            uint32_t off = sw_off(n_base + g * 16 + r, c);
            ldx4(bh[g], bH + off);
            ldx4(bl[g], bL + off);
        }
#pragma unroll
        for (int mt = 0; mt < 2; mt++)
#pragma unroll
            for (int j = 0; j < 4; j++) {
                int g = j >> 1, p = j & 1;
                mma16816(acc[mt][j], ah[mt], bh[g][p], bh[g][p + 2]);
                mma16816(acc[mt][j], ah[mt], bl[g][p], bl[g][p + 2]);
                mma16816(acc[mt][j], al[mt], bh[g][p], bh[g][p + 2]);
            }
    }
}

// ================= preprocessing =================
__global__ void k_split_w(const float* w0, const float* w1, const float* w2,
                          const float* w3, const float* w4, const float* w5) {
    const float* srcs[6] = {w0, w1, w2, w3, w4, w5};
    int ws = blockIdx.y;
    int i = blockIdx.x * 256 + threadIdx.x;
    float v = srcs[ws][i];
    __nv_bfloat16 h = __float2bfloat16(v);
    g_wh[ws][i] = h;
    g_wl[ws][i] = __float2bfloat16(v - __bfloat162float(h));
}

__global__ void k_zero_small(int n) {
    int i = blockIdx.x * blockDim.x + threadIdx.x;
    if (i < n) { g_deg[i] = 0.f; g_hist[i] = 0; }
}

__global__ void k_hist(const int* __restrict__ src, const int* __restrict__ dst,
                       const float* __restrict__ w, int E) {
    int e = blockIdx.x * blockDim.x + threadIdx.x;
    if (e < E) {
        atomicAdd(&g_deg[src[e]], w[e]);
        atomicAdd(&g_hist[dst[e]], 1);
    }
}

// exclusive scan of g_hist -> g_base/g_cursor ; also dis = rsqrt(deg)
__global__ __launch_bounds__(1024) void k_scan(int n) {
    __shared__ int buf[32];
    __shared__ int carry;
    int tid = threadIdx.x, lane = tid & 31, wid = tid >> 5;
    if (tid == 0) carry = 0;
    __syncthreads();
    for (int c0 = 0; c0 < n; c0 += 1024) {
        int i = c0 + tid;
        int v = 0;
        if (i < n) {
            v = g_hist[i];
            float d = g_deg[i];
            g_dis[i] = d > 0.f ? rsqrtf(d) : 0.f;
        }
        int x = v;
#pragma unroll
        for (int o = 1; o < 32; o <<= 1) {
            int y = __shfl_up_sync(~0u, x, o);
            if (lane >= o) x += y;
        }
        if (lane == 31) buf[wid] = x;
        __syncthreads();
        if (wid == 0) {
            int s = buf[lane];
#pragma unroll
            for (int o = 1; o < 32; o <<= 1) {
                int y = __shfl_up_sync(~0u, s, o);
                if (lane >= o) s += y;
            }
            buf[lane] = s;
        }
        __syncthreads();
        int incl = x + (wid > 0 ? buf[wid - 1] : 0);
        int excl = incl - v + carry;
        if (i < n) { g_base[i] = excl; g_cursor[i] = excl; }
        __syncthreads();
        if (tid == 1023) carry += incl;
        __syncthreads();
    }
}

__global__ void k_fill(const int* __restrict__ src, const int* __restrict__ dst,
                       const float* __restrict__ w, int E) {
    int e = blockIdx.x * blockDim.x + threadIdx.x;
    if (e < E) {
        int pos = atomicAdd(&g_cursor[dst[e]], 1);
        g_epack[pos] = make_int2(src[e], __float_as_int(w[e]));
    }
}

// warp per dst node in [lo,hi): accumulate Tx1 & msum from fp32 xh; write bf16 hi/lo
__global__ void k_gather(int lo, int hi) {
    int wd = lo + ((blockIdx.x * blockDim.x + threadIdx.x) >> 5);
    if (wd >= hi) return;
    int lane = threadIdx.x & 31;
    int cnt = g_hist[wd], base = g_base[wd];
    float disd = g_dis[wd];
    float inv = 1.0f / fmaxf((float)cnt, 1.0f);
    float4 at = make_float4(0.f, 0.f, 0.f, 0.f);
    float4 am = make_float4(0.f, 0.f, 0.f, 0.f);
    int j = 0;
    for (; j + 4 <= cnt; j += 4) {
        int2 e[4];
        float4 v[4];
        float w[4], cn[4];
#pragma unroll
        for (int q = 0; q < 4; q++) e[q] = __ldg(g_epack + base + j + q);
#pragma unroll
        for (int q = 0; q < 4; q++)
            v[q] = __ldg((const float4*)g_xh + (size_t)e[q].x * 32 + lane);
#pragma unroll
        for (int q = 0; q < 4; q++) {
            w[q]  = __int_as_float(e[q].y);
            cn[q] = -g_dis[e[q].x] * w[q] * disd;
        }
#pragma unroll
        for (int q = 0; q < 4; q++) {
            at.x = fmaf(cn[q], v[q].x, at.x); at.y = fmaf(cn[q], v[q].y, at.y);
            at.z = fmaf(cn[q], v[q].z, at.z); at.w = fmaf(cn[q], v[q].w, at.w);
            am.x = fmaf(w[q], v[q].x, am.x);  am.y = fmaf(w[q], v[q].y, am.y);
            am.z = fmaf(w[q], v[q].z, am.z);  am.w = fmaf(w[q], v[q].w, am.w);
        }
    }
    for (; j < cnt; j++) {
        int2 e0 = __ldg(g_epack + base + j);
        float4 v0 = __ldg((const float4*)g_xh + (size_t)e0.x * 32 + lane);
        float w0 = __int_as_float(e0.y);
        float c0 = -g_dis[e0.x] * w0 * disd;
        at.x = fmaf(c0, v0.x, at.x); at.y = fmaf(c0, v0.y, at.y);
        at.z = fmaf(c0, v0.z, at.z); at.w = fmaf(c0, v0.w, at.w);
        am.x = fmaf(w0, v0.x, am.x); am.y = fmaf(w0, v0.y, am.y);
        am.z = fmaf(w0, v0.z, am.z); am.w = fmaf(w0, v0.w, am.w);
    }
    am.x *= inv; am.y *= inv; am.z *= inv; am.w *= inv;
    float ft[4] = {at.x, at.y, at.z, at.w};
    float fm[4] = {am.x, am.y, am.z, am.w};
    __nv_bfloat16 th[4], tl[4], mh[4], ml[4];
#pragma unroll
    for (int q = 0; q < 4; q++) {
        th[q] = __float2bfloat16(ft[q]);
        tl[q] = __float2bfloat16(ft[q] - __bfloat162float(th[q]));
        mh[q] = __float2bfloat16(fm[q]);
        ml[q] = __float2bfloat16(fm[q] - __bfloat162float(mh[q]));
    }
    size_t p = (size_t)wd * D + lane * 4;
    *(uint2*)(g_t1h + p) = make_uint2(pk(th[0], th[1]), pk(th[2], th[3]));
    *(uint2*)(g_t1l + p) = make_uint2(pk(tl[0], tl[1]), pk(tl[2], tl[3]));
    *(uint2*)(g_mnh + p) = make_uint2(pk(mh[0], mh[1]), pk(mh[2], mh[3]));
    *(uint2*)(g_mnl + p) = make_uint2(pk(ml[0], ml[1]), pk(ml[2], ml[3]));
}

// ================= GEMM kernels =================
#define SM_G64 (98304)
#define SM_MID (196608)

// xh = x @ Wp^T + bp ; writes fp32 + bf16 hi/lo ; copies x into 'his'
__global__ __launch_bounds__(256, 2) void k_gemm_xh(const float* __restrict__ x,
                                                    const float* __restrict__ bp,
                                                    float* __restrict__ his, int n) {
    extern __shared__ __align__(256) char sb[];
    int tid = threadIdx.x, wid = tid >> 5, lane = tid & 31;
    int m0 = blockIdx.x * 64;
    int m_base = (wid & 1) * 32, n_base = (wid >> 1) * 32;
    uint32_t base = smem_u32(sb);

    load_async<128>(g_wh[WP], 0, base + 32768, tid);
    load_async<128>(g_wl[WP], 0, base + 65536, tid);
    CPA_COMMIT();
    load_split64_copy(x, m0, n, sb, sb + 16384, his, tid);
    CPA_WAIT0();
    __syncthreads();

    float acc[2][4][4];
#pragma unroll
    for (int a = 0; a < 2; a++)
#pragma unroll
        for (int b = 0; b < 4; b++)
#pragma unroll
            for (int q = 0; q < 4; q++) acc[a][b][q] = 0.f;

    warp_phase32(base, base + 16384, base + 32768, base + 65536, m_base, n_base, lane, acc);

    int rr = lane >> 2, cc = 2 * (lane & 3);
#pragma unroll
    for (int mt = 0; mt < 2; mt++) {
#pragma unroll
        for (int j = 0; j < 4; j++) {
            int col = n_base + j * 8 + cc;
            float b0 = __ldg(bp + col), b1 = __ldg(bp + col + 1);
#pragma unroll
            for (int half = 0; half < 2; half++) {
                int row = m0 + m_base + mt * 16 + rr + half * 8;
                if (row < n) {
                    float va = acc[mt][j][2 * half + 0] + b0;
                    float vb = acc[mt][j][2 * half + 1] + b1;
                    size_t p = (size_t)row * D + col;
                    *(float2*)(g_xh + p) = make_float2(va, vb);
                    __nv_bfloat16 ha = __float2bfloat16(va), hb = __float2bfloat16(vb);
                    __nv_bfloat16 la = __float2bfloat16(va - __bfloat162float(ha));
                    __nv_bfloat16 lb = __float2bfloat16(vb - __bfloat162float(hb));
                    *(uint32_t*)(g_xhh + p) = pk(ha, hb);
                    *(uint32_t*)(g_xhl + p) = pk(la, lb);
                }
            }
        }
    }
}

// mid (256 threads): acc1 = xh@Wc0^T + Tx1@Wc1^T ; acc2 = xh@Wroot^T + mean@Wrel^T
// tiles offset by mtile0 (in 64-row tiles)
__global__ __launch_bounds__(256) void k_gemm_mid(const float* __restrict__ bc,
                                                  const float* __restrict__ brel,
                                                  int mtile0, int n) {
    extern __shared__ __align__(256) char sb[];
    int tid = threadIdx.x, wid = tid >> 5, lane = tid & 31;
    int m0 = (mtile0 + blockIdx.x) * 64;
    int m_base = (wid & 1) * 32, n_base = (wid >> 1) * 32;
    uint32_t base = smem_u32(sb);
    uint32_t a1H = base,          a1L = base + 16384;
    uint32_t a2H = base + 32768,  a2L = base + 49152;
    uint32_t waH = base + 65536,  waL = base + 98304;
    uint32_t wbH = base + 131072, wbL = base + 163840;

    float acc1[2][4][4], acc2[2][4][4];
#pragma unroll
    for (int a = 0; a < 2; a++)
#pragma unroll
        for (int b = 0; b < 4; b++)
#pragma unroll
            for (int q = 0; q < 4; q++) { acc1[a][b][q] = 0.f; acc2[a][b][q] = 0.f; }

    load_async<64>(g_xhh, m0, a1H, tid);
    load_async<64>(g_xhl, m0, a1L, tid);
    load_async<64>(g_t1h, m0, a2H, tid);
    load_async<64>(g_t1l, m0, a2L, tid);
    load_async<128>(g_wh[WC0], 0, waH, tid);
    load_async<128>(g_wl[WC0], 0, waL, tid);
    CPA_COMMIT();
    CPA_WAIT0();
    __syncthreads();

    load_async<128>(g_wh[WC1], 0, wbH, tid);
    load_async<128>(g_wl[WC1], 0, wbL, tid);
    CPA_COMMIT();
    warp_phase32(a1H, a1L, waH, waL, m_base, n_base, lane, acc1);
    CPA_WAIT0();
    __syncthreads();

    load_async<128>(g_wh[WROOT], 0, waH, tid);
    load_async<128>(g_wl[WROOT], 0, waL, tid);
    CPA_COMMIT();
    warp_phase32(a2H, a2L, wbH, wbL, m_base, n_base, lane, acc1);
    CPA_WAIT0();
    __syncthreads();

    load_async<64>(g_mnh, m0, a2H, tid);
    load_async<64>(g_mnl, m0, a2L, tid);
    load_async<128>(g_wh[WREL], 0, wbH, tid);
    load_async<128>(g_wl[WREL], 0, wbL, tid);
    CPA_COMMIT();
    warp_phase32(a1H, a1L, waH, waL, m_base, n_base, lane, acc2);
    CPA_WAIT0();
    __syncthreads();

    warp_phase32(a2H, a2L, wbH, wbL, m_base, n_base, lane, acc2);

    int rr = lane >> 2, cc = 2 * (lane & 3);
#pragma unroll
    for (int mt = 0; mt < 2; mt++) {
#pragma unroll
        for (int j = 0; j < 4; j++) {
            int col = n_base + j * 8 + cc;
            float c0 = __ldg(bc + col),   c1 = __ldg(bc + col + 1);
            float r0 = __ldg(brel + col), r1 = __ldg(brel + col + 1);
#pragma unroll
            for (int half = 0; half < 2; half++) {
                int row = m0 + m_base + mt * 16 + rr + half * 8;
                if (row < n) {
                    float v1a = acc1[mt][j][2 * half + 0] + c0;
                    float v1b = acc1[mt][j][2 * half + 1] + c1;
                    float v2a = acc2[mt][j][2 * half + 0] + r0;
                    float v2b = acc2[mt][j][2 * half + 1] + r1;
                    v1a = v1a >= 0.f ? v1a : 0.01f * v1a;
                    v1b = v1b >= 0.f ? v1b : 0.01f * v1b;
                    v2a = v2a >= 0.f ? v2a : 0.01f * v2a;
                    v2b = v2b >= 0.f ? v2b : 0.01f * v2b;
                    float oa = v1a + v2a, ob = v1b + v2b;
                    __nv_bfloat16 ha = __float2bfloat16(oa), hb = __float2bfloat16(ob);
                    __nv_bfloat16 la = __float2bfloat16(oa - __bfloat162float(ha));
                    __nv_bfloat16 lb = __float2bfloat16(ob - __bfloat162float(hb));
                    size_t p = (size_t)row * D + col;
                    *(uint32_t*)(g_o12h + p) = pk(ha, hb);
                    *(uint32_t*)(g_o12l + p) = pk(la, lb);
                }
            }
        }
    }
}

// o3 = o12 @ Wl^T + bl -> fp32 ; tiles offset by mtile0
__global__ __launch_bounds__(256, 2) void k_gemm_fin(const float* __restrict__ bl,
                                                     float* __restrict__ out2,
                                                     int mtile0, int n) {
    extern __shared__ __align__(256) char sb[];
    int tid = threadIdx.x, wid = tid >> 5, lane = tid & 31;
    int m0 = (mtile0 + blockIdx.x) * 64;
    int m_base = (wid & 1) * 32, n_base = (wid >> 1) * 32;
    uint32_t base = smem_u32(sb);

    load_async<64>(g_o12h, m0, base, tid);
    load_async<64>(g_o12l, m0, base + 16384, tid);
    load_async<128>(g_wh[WLIN], 0, base + 32768, tid);
    load_async<128>(g_wl[WLIN], 0, base + 65536, tid);
    CPA_COMMIT();
    CPA_WAIT0();
    __syncthreads();

    float acc[2][4][4];
#pragma unroll
    for (int a = 0; a < 2; a++)
#pragma unroll
        for (int b = 0; b < 4; b++)
#pragma unroll
            for (int q = 0; q < 4; q++) acc[a][b][q] = 0.f;

    warp_phase32(base, base + 16384, base + 32768, base + 65536, m_base, n_base, lane, acc);

    int rr = lane >> 2, cc = 2 * (lane & 3);
#pragma unroll
    for (int mt = 0; mt < 2; mt++) {
#pragma unroll
        for (int j = 0; j < 4; j++) {
            int col = n_base + j * 8 + cc;
            float b0 = __ldg(bl + col), b1 = __ldg(bl + col + 1);
#pragma unroll
            for (int half = 0; half < 2; half++) {
                int row = m0 + m_base + mt * 16 + rr + half * 8;
                if (row < n)
                    *(float2*)(out2 + (size_t)row * D + col) =
                        make_float2(acc[mt][j][2 * half + 0] + b0,
                                    acc[mt][j][2 * half + 1] + b1);
            }
        }
    }
}

// ================= launch =================
extern "C" void kernel_launch(void* const* d_in, const int* in_sizes, int n_in,
                              void* d_out, int out_size) {
    const float* x     = (const float*)d_in[1];
    const int*   ei    = (const int*)  d_in[2];
    const float* ew    = (const float*)d_in[3];
    const float* Wp    = (const float*)d_in[4];
    const float* bp    = (const float*)d_in[5];
    const float* Wc0   = (const float*)d_in[6];
    const float* Wc1   = (const float*)d_in[7];
    const float* bc    = (const float*)d_in[8];
    const float* Wrel  = (const float*)d_in[9];
    const float* brel  = (const float*)d_in[10];
    const float* Wroot = (const float*)d_in[11];
    const float* Wl    = (const float*)d_in[12];
    const float* bl    = (const float*)d_in[13];

    int n = in_sizes[1] / D;
    int E = in_sizes[3];
    float* out = (float*)d_out;
    float* out2 = out + (size_t)n * D;

    cudaFuncSetAttribute(k_gemm_xh,  cudaFuncAttributeMaxDynamicSharedMemorySize, SM_G64);
    cudaFuncSetAttribute(k_gemm_mid, cudaFuncAttributeMaxDynamicSharedMemorySize, SM_MID);
    cudaFuncSetAttribute(k_gemm_fin, cudaFuncAttributeMaxDynamicSharedMemorySize, SM_G64);

    const int C = 4;                 // tail pipeline chunks
    int g64 = (n + 63) / 64;
    int tiles[C], start[C];
    int per = (g64 + C - 1) / C, acc = 0;
    for (int c = 0; c < C; c++) {
        start[c] = acc;
        tiles[c] = (acc + per <= g64) ? per : (g64 - acc);
        if (tiles[c] < 0) tiles[c] = 0;
        acc += tiles[c];
    }

    cudaStream_t s2;
    cudaStreamCreateWithFlags(&s2, cudaStreamNonBlocking);
    cudaEvent_t e1, e_xh, e_g[C], e_done;
    cudaEventCreateWithFlags(&e1,    cudaEventDisableTiming);
    cudaEventCreateWithFlags(&e_xh,  cudaEventDisableTiming);
    for (int c = 0; c < C; c++) cudaEventCreateWithFlags(&e_g[c], cudaEventDisableTiming);
    cudaEventCreateWithFlags(&e_done, cudaEventDisableTiming);

    cudaEventRecord(e1, 0);
    cudaStreamWaitEvent(s2, e1, 0);

    // stream 0: graph preprocessing
    k_zero_small<<<(n + 255) / 256, 256>>>(n);
    k_hist<<<(E + 255) / 256, 256>>>(ei, ei + E, ew, E);
    k_scan<<<1, 1024>>>(n);
    k_fill<<<(E + 255) / 256, 256>>>(ei, ei + E, ew, E);

    // stream s2: weights + first GEMM
    k_split_w<<<dim3(64, 6), 256, 0, s2>>>(Wp, Wc0, Wc1, Wrel, Wroot, Wl);
    k_gemm_xh<<<g64, 256, SM_G64, s2>>>(x, bp, out, n);
    cudaEventRecord(e_xh, s2);

    // stream 0: chunked gathers (need full xh + fill)
    cudaStreamWaitEvent(0, e_xh, 0);
    for (int c = 0; c < C; c++) {
        int lo = start[c] * 64;
        int hi = lo + tiles[c] * 64;
        if (hi > n) hi = n;
        if (hi > lo) k_gather<<<((hi - lo) * 32 + 255) / 256, 256>>>(lo, hi);
        cudaEventRecord(e_g[c], 0);
    }

    // stream s2: per-chunk mid+fin, each behind its gather event
    for (int c = 0; c < C; c++) {
        if (tiles[c] <= 0) continue;
        cudaStreamWaitEvent(s2, e_g[c], 0);
        k_gemm_mid<<<tiles[c], 256, SM_MID, s2>>>(bc, brel, start[c], n);
        k_gemm_fin<<<tiles[c], 256, SM_G64, s2>>>(bl, out2, start[c], n);
    }
    cudaEventRecord(e_done, s2);

    // join
    cudaStreamWaitEvent(0, e_done, 0);

    cudaStreamDestroy(s2);
    cudaEventDestroy(e1);
    cudaEventDestroy(e_xh);
    for (int c = 0; c < C; c++) cudaEventDestroy(e_g[c]);
    cudaEventDestroy(e_done);
}

// round 15
// speedup vs baseline: 1.2255x; 1.2255x over previous
#include <cuda_runtime.h>
#include <cuda_bf16.h>
#include <cstdint>
#include <cstddef>

#define D 128
#define MAXN 50176
#define MAXE 1048576

// ================= global scratch (no allocations allowed) =================
__device__ __align__(16) float g_xh  [(size_t)MAXN * D];           // fp32 xh (gather source)
__device__ __align__(16) __nv_bfloat16 g_xhh[(size_t)MAXN * D];    // xh hi
__device__ __align__(16) __nv_bfloat16 g_xhl[(size_t)MAXN * D];    // xh lo
__device__ __align__(16) __nv_bfloat16 g_t1h[(size_t)MAXN * D];    // Tx1 hi
__device__ __align__(16) __nv_bfloat16 g_t1l[(size_t)MAXN * D];    // Tx1 lo
__device__ __align__(16) __nv_bfloat16 g_mnh[(size_t)MAXN * D];    // mean hi
__device__ __align__(16) __nv_bfloat16 g_mnl[(size_t)MAXN * D];    // mean lo
__device__ __align__(16) __nv_bfloat16 g_o12h[(size_t)MAXN * D];
__device__ __align__(16) __nv_bfloat16 g_o12l[(size_t)MAXN * D];
__device__ __align__(16) __nv_bfloat16 g_wh[6][D * D];
__device__ __align__(16) __nv_bfloat16 g_wl[6][D * D];
__device__ float g_deg [MAXN];
__device__ float g_dis [MAXN];
__device__ int   g_hist[MAXN];
__device__ int   g_base[MAXN];
__device__ int   g_cursor[MAXN];
__device__ __align__(16) int2 g_epack[MAXE];

enum { WP = 0, WC0, WC1, WREL, WROOT, WLIN };

// ================= helpers =================
__device__ __forceinline__ uint32_t smem_u32(const void* p) {
    return (uint32_t)__cvta_generic_to_shared(p);
}
__device__ __forceinline__ uint32_t sw_off(int row, int c16) {
    return (uint32_t)(row * 256 + ((c16 ^ (row & 7)) << 4));
}
__device__ __forceinline__ void ldx4(uint32_t r[4], uint32_t a) {
    asm volatile("ldmatrix.sync.aligned.m8n8.x4.shared.b16 {%0,%1,%2,%3}, [%4];"
                 : "=r"(r[0]), "=r"(r[1]), "=r"(r[2]), "=r"(r[3]) : "r"(a));
}
__device__ __forceinline__ void mma16816(float c[4], const uint32_t a[4],
                                         uint32_t b0, uint32_t b1) {
    asm volatile("mma.sync.aligned.m16n8k16.row.col.f32.bf16.bf16.f32 "
                 "{%0,%1,%2,%3}, {%4,%5,%6,%7}, {%8,%9}, {%0,%1,%2,%3};"
                 : "+f"(c[0]), "+f"(c[1]), "+f"(c[2]), "+f"(c[3])
                 : "r"(a[0]), "r"(a[1]), "r"(a[2]), "r"(a[3]), "r"(b0), "r"(b1));
}
__device__ __forceinline__ uint32_t pk(__nv_bfloat16 a, __nv_bfloat16 b) {
    return (uint32_t)__bfloat16_as_ushort(a) | ((uint32_t)__bfloat16_as_ushort(b) << 16);
}
__device__ __forceinline__ void cpa16(uint32_t dst, const void* src) {
    asm volatile("cp.async.cg.shared.global [%0], [%1], 16;" :: "r"(dst), "l"(src));
}
#define CPA_COMMIT() asm volatile("cp.async.commit_group;" ::: "memory")
#define CPA_WAIT0()  asm volatile("cp.async.wait_group 0;" ::: "memory")

template<int ROWS>
__device__ __forceinline__ void load_async(const __nv_bfloat16* __restrict__ src, int m0,
                                           uint32_t dst, int tid) {
#pragma unroll
    for (int t = 0; t < ROWS * 16 / 256; t++) {
        int idx = tid + t * 256;
        int row = idx >> 4, c16 = idx & 15;
        cpa16(dst + sw_off(row, c16), src + (size_t)(m0 + row) * D + c16 * 8);
    }
}

// load 64x128 fp32 tile (row guard), split hi/lo swizzled; also copy rows to 'his'
__device__ __forceinline__ void load_split64_copy(const float* __restrict__ src, int m0, int n,
                                                  char* ah, char* al,
                                                  float* __restrict__ his, int tid) {
#pragma unroll
    for (int t = 0; t < 4; t++) {
        int idx = tid + t * 256;
        int row = idx >> 4, c16 = idx & 15;
        int gr = m0 + row;
        float4 v0 = make_float4(0.f, 0.f, 0.f, 0.f), v1 = v0;
        if (gr < n) {
            const float* p = src + (size_t)gr * D + c16 * 8;
            v0 = *(const float4*)p;
            v1 = *(const float4*)(p + 4);
            float* q = his + (size_t)gr * D + c16 * 8;
            *(float4*)q = v0;
            *(float4*)(q + 4) = v1;
        }
        float f[8] = {v0.x, v0.y, v0.z, v0.w, v1.x, v1.y, v1.z, v1.w};
        __nv_bfloat16 h[8], l[8];
#pragma unroll
        for (int q = 0; q < 8; q++) {
            h[q] = __float2bfloat16(f[q]);
            l[q] = __float2bfloat16(f[q] - __bfloat162float(h[q]));
        }
        uint32_t off = sw_off(row, c16);
        *(uint4*)(ah + off) = make_uint4(pk(h[0],h[1]), pk(h[2],h[3]), pk(h[4],h[5]), pk(h[6],h[7]));
        *(uint4*)(al + off) = make_uint4(pk(l[0],l[1]), pk(l[2],l[3]), pk(l[4],l[5]), pk(l[6],l[7]));
    }
}

// warp tile 32(m) x 32(n), K=128; acc += Ah*Bh + Ah*Bl + Al*Bh
__device__ __forceinline__ void warp_phase32(
    uint32_t aH, uint32_t aL, uint32_t bH, uint32_t bL,
    int m_base, int n_base, int lane, float acc[2][4][4])
{
    int r = lane & 15, chs = lane >> 4;
#pragma unroll
    for (int kk = 0; kk < 8; kk++) {
        int c = 2 * kk + chs;
        uint32_t ah[2][4], al[2][4], bh[2][4], bl[2][4];
#pragma unroll
        for (int mt = 0; mt < 2; mt++) {
            uint32_t off = sw_off(m_base + mt * 16 + r, c);
            ldx4(ah[mt], aH + off);
            ldx4(al[mt], aL + off);
        }
#pragma unroll
        for (int g = 0; g < 2; g++) {
            uint32_t off = sw_off(n_base + g * 16 + r, c);
            ldx4(bh[g], bH + off);
            ldx4(bl[g], bL + off);
        }
#pragma unroll
        for (int mt = 0; mt < 2; mt++)
#pragma unroll
            for (int j = 0; j < 4; j++) {
                int g = j >> 1, p = j & 1;
                mma16816(acc[mt][j], ah[mt], bh[g][p], bh[g][p + 2]);
                mma16816(acc[mt][j], ah[mt], bl[g][p], bl[g][p + 2]);
                mma16816(acc[mt][j], al[mt], bh[g][p], bh[g][p + 2]);
            }
    }
}

// ================= preprocessing =================
__global__ void k_split_w(const float* w0, const float* w1, const float* w2,
                          const float* w3, const float* w4, const float* w5) {
    const float* srcs[6] = {w0, w1, w2, w3, w4, w5};
    int ws = blockIdx.y;
    int i = blockIdx.x * 256 + threadIdx.x;
    float v = srcs[ws][i];
    __nv_bfloat16 h = __float2bfloat16(v);
    g_wh[ws][i] = h;
    g_wl[ws][i] = __float2bfloat16(v - __bfloat162float(h));
}

__global__ void k_zero_small(int n) {
    int i = blockIdx.x * blockDim.x + threadIdx.x;
    if (i < n) { g_deg[i] = 0.f; g_hist[i] = 0; }
}

__global__ void k_hist(const int* __restrict__ src, const int* __restrict__ dst,
                       const float* __restrict__ w, int E) {
    int e = blockIdx.x * blockDim.x + threadIdx.x;
    if (e < E) {
        atomicAdd(&g_deg[src[e]], w[e]);
        atomicAdd(&g_hist[dst[e]], 1);
    }
}

// exclusive scan of g_hist -> g_base/g_cursor ; also dis = rsqrt(deg)
__global__ __launch_bounds__(1024) void k_scan(int n) {
    __shared__ int buf[32];
    __shared__ int carry;
    int tid = threadIdx.x, lane = tid & 31, wid = tid >> 5;
    if (tid == 0) carry = 0;
    __syncthreads();
    for (int c0 = 0; c0 < n; c0 += 1024) {
        int i = c0 + tid;
        int v = 0;
        if (i < n) {
            v = g_hist[i];
            float d = g_deg[i];
            g_dis[i] = d > 0.f ? rsqrtf(d) : 0.f;
        }
        int x = v;
#pragma unroll
        for (int o = 1; o < 32; o <<= 1) {
            int y = __shfl_up_sync(~0u, x, o);
            if (lane >= o) x += y;
        }
        if (lane == 31) buf[wid] = x;
        __syncthreads();
        if (wid == 0) {
            int s = buf[lane];
#pragma unroll
            for (int o = 1; o < 32; o <<= 1) {
                int y = __shfl_up_sync(~0u, s, o);
                if (lane >= o) s += y;
            }
            buf[lane] = s;
        }
        __syncthreads();
        int incl = x + (wid > 0 ? buf[wid - 1] : 0);
        int excl = incl - v + carry;
        if (i < n) { g_base[i] = excl; g_cursor[i] = excl; }
        __syncthreads();
        if (tid == 1023) carry += incl;
        __syncthreads();
    }
}

__global__ void k_fill(const int* __restrict__ src, const int* __restrict__ dst,
                       const float* __restrict__ w, int E) {
    int e = blockIdx.x * blockDim.x + threadIdx.x;
    if (e < E) {
        int pos = atomicAdd(&g_cursor[dst[e]], 1);
        g_epack[pos] = make_int2(src[e], __float_as_int(w[e]));
    }
}

// warp per dst node in [lo,hi): accumulate Tx1 & msum from fp32 xh; write bf16 hi/lo
__global__ void k_gather(int lo, int hi) {
    int wd = lo + ((blockIdx.x * blockDim.x + threadIdx.x) >> 5);
    if (wd >= hi) return;
    int lane = threadIdx.x & 31;
    int cnt = g_hist[wd], base = g_base[wd];
    float disd = g_dis[wd];
    float inv = 1.0f / fmaxf((float)cnt, 1.0f);
    float4 at = make_float4(0.f, 0.f, 0.f, 0.f);
    float4 am = make_float4(0.f, 0.f, 0.f, 0.f);
    int j = 0;
    for (; j + 4 <= cnt; j += 4) {
        int2 e[4];
        float4 v[4];
        float w[4], cn[4];
#pragma unroll
        for (int q = 0; q < 4; q++) e[q] = __ldg(g_epack + base + j + q);
#pragma unroll
        for (int q = 0; q < 4; q++)
            v[q] = __ldg((const float4*)g_xh + (size_t)e[q].x * 32 + lane);
#pragma unroll
        for (int q = 0; q < 4; q++) {
            w[q]  = __int_as_float(e[q].y);
            cn[q] = -g_dis[e[q].x] * w[q] * disd;
        }
#pragma unroll
        for (int q = 0; q < 4; q++) {
            at.x = fmaf(cn[q], v[q].x, at.x); at.y = fmaf(cn[q], v[q].y, at.y);
            at.z = fmaf(cn[q], v[q].z, at.z); at.w = fmaf(cn[q], v[q].w, at.w);
            am.x = fmaf(w[q], v[q].x, am.x);  am.y = fmaf(w[q], v[q].y, am.y);
            am.z = fmaf(w[q], v[q].z, am.z);  am.w = fmaf(w[q], v[q].w, am.w);
        }
    }
    for (; j < cnt; j++) {
        int2 e0 = __ldg(g_epack + base + j);
        float4 v0 = __ldg((const float4*)g_xh + (size_t)e0.x * 32 + lane);
        float w0 = __int_as_float(e0.y);
        float c0 = -g_dis[e0.x] * w0 * disd;
        at.x = fmaf(c0, v0.x, at.x); at.y = fmaf(c0, v0.y, at.y);
        at.z = fmaf(c0, v0.z, at.z); at.w = fmaf(c0, v0.w, at.w);
        am.x = fmaf(w0, v0.x, am.x); am.y = fmaf(w0, v0.y, am.y);
        am.z = fmaf(w0, v0.z, am.z); am.w = fmaf(w0, v0.w, am.w);
    }
    am.x *= inv; am.y *= inv; am.z *= inv; am.w *= inv;
    float ft[4] = {at.x, at.y, at.z, at.w};
    float fm[4] = {am.x, am.y, am.z, am.w};
    __nv_bfloat16 th[4], tl[4], mh[4], ml[4];
#pragma unroll
    for (int q = 0; q < 4; q++) {
        th[q] = __float2bfloat16(ft[q]);
        tl[q] = __float2bfloat16(ft[q] - __bfloat162float(th[q]));
        mh[q] = __float2bfloat16(fm[q]);
        ml[q] = __float2bfloat16(fm[q] - __bfloat162float(mh[q]));
    }
    size_t p = (size_t)wd * D + lane * 4;
    *(uint2*)(g_t1h + p) = make_uint2(pk(th[0], th[1]), pk(th[2], th[3]));
    *(uint2*)(g_t1l + p) = make_uint2(pk(tl[0], tl[1]), pk(tl[2], tl[3]));
    *(uint2*)(g_mnh + p) = make_uint2(pk(mh[0], mh[1]), pk(mh[2], mh[3]));
    *(uint2*)(g_mnl + p) = make_uint2(pk(ml[0], ml[1]), pk(ml[2], ml[3]));
}

// ================= GEMM kernels =================
#define SM_G64 (98304)
#define SM_MID (196608)

// xh = x @ Wp^T + bp ; writes fp32 + bf16 hi/lo ; copies x into 'his'
__global__ __launch_bounds__(256, 2) void k_gemm_xh(const float* __restrict__ x,
                                                    const float* __restrict__ bp,
                                                    float* __restrict__ his, int n) {
    extern __shared__ __align__(256) char sb[];
    int tid = threadIdx.x, wid = tid >> 5, lane = tid & 31;
    int m0 = blockIdx.x * 64;
    int m_base = (wid & 1) * 32, n_base = (wid >> 1) * 32;
    uint32_t base = smem_u32(sb);

    load_async<128>(g_wh[WP], 0, base + 32768, tid);
    load_async<128>(g_wl[WP], 0, base + 65536, tid);
    CPA_COMMIT();
    load_split64_copy(x, m0, n, sb, sb + 16384, his, tid);
    CPA_WAIT0();
    __syncthreads();

    float acc[2][4][4];
#pragma unroll
    for (int a = 0; a < 2; a++)
#pragma unroll
        for (int b = 0; b < 4; b++)
#pragma unroll
            for (int q = 0; q < 4; q++) acc[a][b][q] = 0.f;

    warp_phase32(base, base + 16384, base + 32768, base + 65536, m_base, n_base, lane, acc);

    int rr = lane >> 2, cc = 2 * (lane & 3);
#pragma unroll
    for (int mt = 0; mt < 2; mt++) {
#pragma unroll
        for (int j = 0; j < 4; j++) {
            int col = n_base + j * 8 + cc;
            float b0 = __ldg(bp + col), b1 = __ldg(bp + col + 1);
#pragma unroll
            for (int half = 0; half < 2; half++) {
                int row = m0 + m_base + mt * 16 + rr + half * 8;
                if (row < n) {
                    float va = acc[mt][j][2 * half + 0] + b0;
                    float vb = acc[mt][j][2 * half + 1] + b1;
                    size_t p = (size_t)row * D + col;
                    *(float2*)(g_xh + p) = make_float2(va, vb);
                    __nv_bfloat16 ha = __float2bfloat16(va), hb = __float2bfloat16(vb);
                    __nv_bfloat16 la = __float2bfloat16(va - __bfloat162float(ha));
                    __nv_bfloat16 lb = __float2bfloat16(vb - __bfloat162float(hb));
                    *(uint32_t*)(g_xhh + p) = pk(ha, hb);
                    *(uint32_t*)(g_xhl + p) = pk(la, lb);
                }
            }
        }
    }
}

// mid (256 threads): acc1 = xh@Wc0^T + Tx1@Wc1^T ; acc2 = xh@Wroot^T + mean@Wrel^T
// tiles offset by mtile0 (in 64-row tiles)
__global__ __launch_bounds__(256) void k_gemm_mid(const float* __restrict__ bc,
                                                  const float* __restrict__ brel,
                                                  int mtile0, int n) {
    extern __shared__ __align__(256) char sb[];
    int tid = threadIdx.x, wid = tid >> 5, lane = tid & 31;
    int m0 = (mtile0 + blockIdx.x) * 64;
    int m_base = (wid & 1) * 32, n_base = (wid >> 1) * 32;
    uint32_t base = smem_u32(sb);
    uint32_t a1H = base,          a1L = base + 16384;
    uint32_t a2H = base + 32768,  a2L = base + 49152;
    uint32_t waH = base + 65536,  waL = base + 98304;
    uint32_t wbH = base + 131072, wbL = base + 163840;

    float acc1[2][4][4], acc2[2][4][4];
#pragma unroll
    for (int a = 0; a < 2; a++)
#pragma unroll
        for (int b = 0; b < 4; b++)
#pragma unroll
            for (int q = 0; q < 4; q++) { acc1[a][b][q] = 0.f; acc2[a][b][q] = 0.f; }

    load_async<64>(g_xhh, m0, a1H, tid);
    load_async<64>(g_xhl, m0, a1L, tid);
    load_async<64>(g_t1h, m0, a2H, tid);
    load_async<64>(g_t1l, m0, a2L, tid);
    load_async<128>(g_wh[WC0], 0, waH, tid);
    load_async<128>(g_wl[WC0], 0, waL, tid);
    CPA_COMMIT();
    CPA_WAIT0();
    __syncthreads();

    load_async<128>(g_wh[WC1], 0, wbH, tid);
    load_async<128>(g_wl[WC1], 0, wbL, tid);
    CPA_COMMIT();
    warp_phase32(a1H, a1L, waH, waL, m_base, n_base, lane, acc1);
    CPA_WAIT0();
    __syncthreads();

    load_async<128>(g_wh[WROOT], 0, waH, tid);
    load_async<128>(g_wl[WROOT], 0, waL, tid);
    CPA_COMMIT();
    warp_phase32(a2H, a2L, wbH, wbL, m_base, n_base, lane, acc1);
    CPA_WAIT0();
    __syncthreads();

    load_async<64>(g_mnh, m0, a2H, tid);
    load_async<64>(g_mnl, m0, a2L, tid);
    load_async<128>(g_wh[WREL], 0, wbH, tid);
    load_async<128>(g_wl[WREL], 0, wbL, tid);
    CPA_COMMIT();
    warp_phase32(a1H, a1L, waH, waL, m_base, n_base, lane, acc2);
    CPA_WAIT0();
    __syncthreads();

    warp_phase32(a2H, a2L, wbH, wbL, m_base, n_base, lane, acc2);

    int rr = lane >> 2, cc = 2 * (lane & 3);
#pragma unroll
    for (int mt = 0; mt < 2; mt++) {
#pragma unroll
        for (int j = 0; j < 4; j++) {
            int col = n_base + j * 8 + cc;
            float c0 = __ldg(bc + col),   c1 = __ldg(bc + col + 1);
            float r0 = __ldg(brel + col), r1 = __ldg(brel + col + 1);
#pragma unroll
            for (int half = 0; half < 2; half++) {
                int row = m0 + m_base + mt * 16 + rr + half * 8;
                if (row < n) {
                    float v1a = acc1[mt][j][2 * half + 0] + c0;
                    float v1b = acc1[mt][j][2 * half + 1] + c1;
                    float v2a = acc2[mt][j][2 * half + 0] + r0;
                    float v2b = acc2[mt][j][2 * half + 1] + r1;
                    v1a = v1a >= 0.f ? v1a : 0.01f * v1a;
                    v1b = v1b >= 0.f ? v1b : 0.01f * v1b;
                    v2a = v2a >= 0.f ? v2a : 0.01f * v2a;
                    v2b = v2b >= 0.f ? v2b : 0.01f * v2b;
                    float oa = v1a + v2a, ob = v1b + v2b;
                    __nv_bfloat16 ha = __float2bfloat16(oa), hb = __float2bfloat16(ob);
                    __nv_bfloat16 la = __float2bfloat16(oa - __bfloat162float(ha));
                    __nv_bfloat16 lb = __float2bfloat16(ob - __bfloat162float(hb));
                    size_t p = (size_t)row * D + col;
                    *(uint32_t*)(g_o12h + p) = pk(ha, hb);
                    *(uint32_t*)(g_o12l + p) = pk(la, lb);
                }
            }
        }
    }
}

// o3 = o12 @ Wl^T + bl -> fp32 ; tiles offset by mtile0
__global__ __launch_bounds__(256, 2) void k_gemm_fin(const float* __restrict__ bl,
                                                     float* __restrict__ out2,
                                                     int mtile0, int n) {
    extern __shared__ __align__(256) char sb[];
    int tid = threadIdx.x, wid = tid >> 5, lane = tid & 31;
    int m0 = (mtile0 + blockIdx.x) * 64;
    int m_base = (wid & 1) * 32, n_base = (wid >> 1) * 32;
    uint32_t base = smem_u32(sb);

    load_async<64>(g_o12h, m0, base, tid);
    load_async<64>(g_o12l, m0, base + 16384, tid);
    load_async<128>(g_wh[WLIN], 0, base + 32768, tid);
    load_async<128>(g_wl[WLIN], 0, base + 65536, tid);
    CPA_COMMIT();
    CPA_WAIT0();
    __syncthreads();

    float acc[2][4][4];
#pragma unroll
    for (int a = 0; a < 2; a++)
#pragma unroll
        for (int b = 0; b < 4; b++)
#pragma unroll
            for (int q = 0; q < 4; q++) acc[a][b][q] = 0.f;

    warp_phase32(base, base + 16384, base + 32768, base + 65536, m_base, n_base, lane, acc);

    int rr = lane >> 2, cc = 2 * (lane & 3);
#pragma unroll
    for (int mt = 0; mt < 2; mt++) {
#pragma unroll
        for (int j = 0; j < 4; j++) {
            int col = n_base + j * 8 + cc;
            float b0 = __ldg(bl + col), b1 = __ldg(bl + col + 1);
#pragma unroll
            for (int half = 0; half < 2; half++) {
                int row = m0 + m_base + mt * 16 + rr + half * 8;
                if (row < n)
                    *(float2*)(out2 + (size_t)row * D + col) =
                        make_float2(acc[mt][j][2 * half + 0] + b0,
                                    acc[mt][j][2 * half + 1] + b1);
            }
        }
    }
}

// ================= launch =================
extern "C" void kernel_launch(void* const* d_in, const int* in_sizes, int n_in,
                              void* d_out, int out_size) {
    const float* x     = (const float*)d_in[1];
    const int*   ei    = (const int*)  d_in[2];
    const float* ew    = (const float*)d_in[3];
    const float* Wp    = (const float*)d_in[4];
    const float* bp    = (const float*)d_in[5];
    const float* Wc0   = (const float*)d_in[6];
    const float* Wc1   = (const float*)d_in[7];
    const float* bc    = (const float*)d_in[8];
    const float* Wrel  = (const float*)d_in[9];
    const float* brel  = (const float*)d_in[10];
    const float* Wroot = (const float*)d_in[11];
    const float* Wl    = (const float*)d_in[12];
    const float* bl    = (const float*)d_in[13];

    int n = in_sizes[1] / D;
    int E = in_sizes[3];
    float* out = (float*)d_out;
    float* out2 = out + (size_t)n * D;

    cudaFuncSetAttribute(k_gemm_xh,  cudaFuncAttributeMaxDynamicSharedMemorySize, SM_G64);
    cudaFuncSetAttribute(k_gemm_mid, cudaFuncAttributeMaxDynamicSharedMemorySize, SM_MID);
    cudaFuncSetAttribute(k_gemm_fin, cudaFuncAttributeMaxDynamicSharedMemorySize, SM_G64);

    int g64 = (n + 63) / 64;
    int gA = (g64 * 5 + 4) / 8;      // ~62.5% of tiles to stream s2 (starts earlier)
    if (gA > g64) gA = g64;
    int gB = g64 - gA;               // remainder on stream 0
    int h  = gA * 64;                // node split point (rows in half A)
    if (h > n) h = n;

    cudaStream_t s2;
    cudaStreamCreateWithFlags(&s2, cudaStreamNonBlocking);
    cudaEvent_t e1, e_xh, e_gA, e_done;
    cudaEventCreateWithFlags(&e1,    cudaEventDisableTiming);
    cudaEventCreateWithFlags(&e_xh,  cudaEventDisableTiming);
    cudaEventCreateWithFlags(&e_gA,  cudaEventDisableTiming);
    cudaEventCreateWithFlags(&e_done,cudaEventDisableTiming);

    cudaEventRecord(e1, 0);
    cudaStreamWaitEvent(s2, e1, 0);

    // stream 0: graph preprocessing
    k_zero_small<<<(n + 255) / 256, 256>>>(n);
    k_hist<<<(E + 255) / 256, 256>>>(ei, ei + E, ew, E);
    k_scan<<<1, 1024>>>(n);
    k_fill<<<(E + 255) / 256, 256>>>(ei, ei + E, ew, E);

    // stream s2: weights + first GEMM
    k_split_w<<<dim3(64, 6), 256, 0, s2>>>(Wp, Wc0, Wc1, Wrel, Wroot, Wl);
    k_gemm_xh<<<g64, 256, SM_G64, s2>>>(x, bp, out, n);
    cudaEventRecord(e_xh, s2);

    // stream 0: gather chunk A (needs full xh + fill)
    cudaStreamWaitEvent(0, e_xh, 0);
    k_gather<<<(h * 32 + 255) / 256, 256>>>(0, h);
    cudaEventRecord(e_gA, 0);

    // stream 0 continues: gather chunk B, then mid/fin for chunk B
    if (n > h) k_gather<<<((n - h) * 32 + 255) / 256, 256>>>(h, n);
    if (gB > 0) {
        k_gemm_mid<<<gB, 256, SM_MID>>>(bc, brel, gA, n);
        k_gemm_fin<<<gB, 256, SM_G64>>>(bl, out2, gA, n);
    }

    // stream s2: mid/fin for chunk A (overlaps gather B / mid B on stream 0)
    cudaStreamWaitEvent(s2, e_gA, 0);
    k_gemm_mid<<<gA, 256, SM_MID, s2>>>(bc, brel, 0, n);
    k_gemm_fin<<<gA, 256, SM_G64, s2>>>(bl, out2, 0, n);
    cudaEventRecord(e_done, s2);

    // join
    cudaStreamWaitEvent(0, e_done, 0);

    cudaStreamDestroy(s2);
    cudaEventDestroy(e1);
    cudaEventDestroy(e_xh);
    cudaEventDestroy(e_gA);
    cudaEventDestroy(e_done);
}

// round 16
// speedup vs baseline: 1.4332x; 1.1695x over previous
#include <cuda_runtime.h>
#include <cuda_bf16.h>
#include <cstdint>
#include <cstddef>

#define D 128
#define MAXN 50176
#define MAXE 1048576

// ================= global scratch (no allocations allowed) =================
__device__ __align__(16) float g_xh  [(size_t)MAXN * D];           // fp32 xh (gather source)
__device__ __align__(16) __nv_bfloat16 g_xhh[(size_t)MAXN * D];    // xh hi
__device__ __align__(16) __nv_bfloat16 g_xhl[(size_t)MAXN * D];    // xh lo
__device__ __align__(16) __nv_bfloat16 g_t1h[(size_t)MAXN * D];    // Tx1 hi
__device__ __align__(16) __nv_bfloat16 g_t1l[(size_t)MAXN * D];    // Tx1 lo
__device__ __align__(16) __nv_bfloat16 g_mnh[(size_t)MAXN * D];    // mean hi
__device__ __align__(16) __nv_bfloat16 g_mnl[(size_t)MAXN * D];    // mean lo
__device__ __align__(16) __nv_bfloat16 g_o12h[(size_t)MAXN * D];
__device__ __align__(16) __nv_bfloat16 g_o12l[(size_t)MAXN * D];
__device__ __align__(16) __nv_bfloat16 g_wh[6][D * D];
__device__ __align__(16) __nv_bfloat16 g_wl[6][D * D];
__device__ float g_deg [MAXN];
__device__ float g_dis [MAXN];
__device__ int   g_hist[MAXN];
__device__ int   g_base[MAXN];
__device__ int   g_cursor[MAXN];
__device__ int   g_bsum[64];
__device__ __align__(16) int2 g_epack[MAXE];

enum { WP = 0, WC0, WC1, WREL, WROOT, WLIN };

// ================= helpers =================
__device__ __forceinline__ uint32_t smem_u32(const void* p) {
    return (uint32_t)__cvta_generic_to_shared(p);
}
__device__ __forceinline__ uint32_t sw_off(int row, int c16) {
    return (uint32_t)(row * 256 + ((c16 ^ (row & 7)) << 4));
}
__device__ __forceinline__ void ldx4(uint32_t r[4], uint32_t a) {
    asm volatile("ldmatrix.sync.aligned.m8n8.x4.shared.b16 {%0,%1,%2,%3}, [%4];"
                 : "=r"(r[0]), "=r"(r[1]), "=r"(r[2]), "=r"(r[3]) : "r"(a));
}
__device__ __forceinline__ void mma16816(float c[4], const uint32_t a[4],
                                         uint32_t b0, uint32_t b1) {
    asm volatile("mma.sync.aligned.m16n8k16.row.col.f32.bf16.bf16.f32 "
                 "{%0,%1,%2,%3}, {%4,%5,%6,%7}, {%8,%9}, {%0,%1,%2,%3};"
                 : "+f"(c[0]), "+f"(c[1]), "+f"(c[2]), "+f"(c[3])
                 : "r"(a[0]), "r"(a[1]), "r"(a[2]), "r"(a[3]), "r"(b0), "r"(b1));
}
__device__ __forceinline__ uint32_t pk(__nv_bfloat16 a, __nv_bfloat16 b) {
    return (uint32_t)__bfloat16_as_ushort(a) | ((uint32_t)__bfloat16_as_ushort(b) << 16);
}
__device__ __forceinline__ void cpa16(uint32_t dst, const void* src) {
    asm volatile("cp.async.cg.shared.global [%0], [%1], 16;" :: "r"(dst), "l"(src));
}
#define CPA_COMMIT() asm volatile("cp.async.commit_group;" ::: "memory")
#define CPA_WAIT0()  asm volatile("cp.async.wait_group 0;" ::: "memory")

template<int ROWS>
__device__ __forceinline__ void load_async(const __nv_bfloat16* __restrict__ src, int m0,
                                           uint32_t dst, int tid) {
#pragma unroll
    for (int t = 0; t < ROWS * 16 / 256; t++) {
        int idx = tid + t * 256;
        int row = idx >> 4, c16 = idx & 15;
        cpa16(dst + sw_off(row, c16), src + (size_t)(m0 + row) * D + c16 * 8);
    }
}

// load 64x128 fp32 tile (row guard), split hi/lo swizzled; also copy rows to 'his'
__device__ __forceinline__ void load_split64_copy(const float* __restrict__ src, int m0, int n,
                                                  char* ah, char* al,
                                                  float* __restrict__ his, int tid) {
#pragma unroll
    for (int t = 0; t < 4; t++) {
        int idx = tid + t * 256;
        int row = idx >> 4, c16 = idx & 15;
        int gr = m0 + row;
        float4 v0 = make_float4(0.f, 0.f, 0.f, 0.f), v1 = v0;
        if (gr < n) {
            const float* p = src + (size_t)gr * D + c16 * 8;
            v0 = *(const float4*)p;
            v1 = *(const float4*)(p + 4);
            float* q = his + (size_t)gr * D + c16 * 8;
            *(float4*)q = v0;
            *(float4*)(q + 4) = v1;
        }
        float f[8] = {v0.x, v0.y, v0.z, v0.w, v1.x, v1.y, v1.z, v1.w};
        __nv_bfloat16 h[8], l[8];
#pragma unroll
        for (int q = 0; q < 8; q++) {
            h[q] = __float2bfloat16(f[q]);
            l[q] = __float2bfloat16(f[q] - __bfloat162float(h[q]));
        }
        uint32_t off = sw_off(row, c16);
        *(uint4*)(ah + off) = make_uint4(pk(h[0],h[1]), pk(h[2],h[3]), pk(h[4],h[5]), pk(h[6],h[7]));
        *(uint4*)(al + off) = make_uint4(pk(l[0],l[1]), pk(l[2],l[3]), pk(l[4],l[5]), pk(l[6],l[7]));
    }
}

// warp tile 32(m) x 32(n), K=128; acc += Ah*Bh + Ah*Bl + Al*Bh
__device__ __forceinline__ void warp_phase32(
    uint32_t aH, uint32_t aL, uint32_t bH, uint32_t bL,
    int m_base, int n_base, int lane, float acc[2][4][4])
{
    int r = lane & 15, chs = lane >> 4;
#pragma unroll
    for (int kk = 0; kk < 8; kk++) {
        int c = 2 * kk + chs;
        uint32_t ah[2][4], al[2][4], bh[2][4], bl[2][4];
#pragma unroll
        for (int mt = 0; mt < 2; mt++) {
            uint32_t off = sw_off(m_base + mt * 16 + r, c);
            ldx4(ah[mt], aH + off);
            ldx4(al[mt], aL + off);
        }
#pragma unroll
        for (int g = 0; g < 2; g++) {
            uint32_t off = sw_off(n_base + g * 16 + r, c);
            ldx4(bh[g], bH + off);
            ldx4(bl[g], bL + off);
        }
#pragma unroll
        for (int mt = 0; mt < 2; mt++)
#pragma unroll
            for (int j = 0; j < 4; j++) {
                int g = j >> 1, p = j & 1;
                mma16816(acc[mt][j], ah[mt], bh[g][p], bh[g][p + 2]);
                mma16816(acc[mt][j], ah[mt], bl[g][p], bl[g][p + 2]);
                mma16816(acc[mt][j], al[mt], bh[g][p], bh[g][p + 2]);
            }
    }
}

// ================= preprocessing =================
__global__ void k_split_w(const float* w0, const float* w1, const float* w2,
                          const float* w3, const float* w4, const float* w5) {
    const float* srcs[6] = {w0, w1, w2, w3, w4, w5};
    int ws = blockIdx.y;
    int i = blockIdx.x * 256 + threadIdx.x;
    float v = srcs[ws][i];
    __nv_bfloat16 h = __float2bfloat16(v);
    g_wh[ws][i] = h;
    g_wl[ws][i] = __float2bfloat16(v - __bfloat162float(h));
}

__global__ void k_zero_small(int n) {
    int i = blockIdx.x * blockDim.x + threadIdx.x;
    if (i < n) { g_deg[i] = 0.f; g_hist[i] = 0; }
}

__global__ void k_hist(const int* __restrict__ src, const int* __restrict__ dst,
                       const float* __restrict__ w, int E) {
    int e = blockIdx.x * blockDim.x + threadIdx.x;
    if (e < E) {
        atomicAdd(&g_deg[src[e]], w[e]);
        atomicAdd(&g_hist[dst[e]], 1);
    }
}

// hierarchical scan stage A: per-block local exclusive scan of g_hist -> g_base,
// block total -> g_bsum ; also dis = rsqrt(deg)
__global__ __launch_bounds__(1024) void k_scan_local(int n) {
    __shared__ int buf[32];
    int tid = threadIdx.x, lane = tid & 31, wid = tid >> 5;
    int i = blockIdx.x * 1024 + tid;
    int v = 0;
    if (i < n) {
        v = g_hist[i];
        float d = g_deg[i];
        g_dis[i] = d > 0.f ? rsqrtf(d) : 0.f;
    }
    int x = v;
#pragma unroll
    for (int o = 1; o < 32; o <<= 1) {
        int y = __shfl_up_sync(~0u, x, o);
        if (lane >= o) x += y;
    }
    if (lane == 31) buf[wid] = x;
    __syncthreads();
    if (wid == 0) {
        int s = buf[lane];
#pragma unroll
        for (int o = 1; o < 32; o <<= 1) {
            int y = __shfl_up_sync(~0u, s, o);
            if (lane >= o) s += y;
        }
        buf[lane] = s;
    }
    __syncthreads();
    int incl = x + (wid > 0 ? buf[wid - 1] : 0);
    if (i < n) g_base[i] = incl - v;           // local exclusive
    if (tid == 0) g_bsum[blockIdx.x] = buf[31]; // block total
}

// stage B: exclusive scan of block sums (nb <= 64, 2 warps)
__global__ void k_scan_bsum(int nb) {
    __shared__ int wtot[2];
    int t = threadIdx.x, lane = t & 31, w = t >> 5;
    int v = (t < nb) ? g_bsum[t] : 0;
    int x = v;
#pragma unroll
    for (int o = 1; o < 32; o <<= 1) {
        int y = __shfl_up_sync(~0u, x, o);
        if (lane >= o) x += y;
    }
    if (lane == 31) wtot[w] = x;
    __syncthreads();
    int add = (w == 1) ? wtot[0] : 0;
    if (t < nb) g_bsum[t] = x - v + add;       // exclusive
}

// stage C: add block offsets, produce base + cursor
__global__ __launch_bounds__(1024) void k_scan_add(int n) {
    int i = blockIdx.x * 1024 + threadIdx.x;
    if (i < n) {
        int b = g_base[i] + g_bsum[blockIdx.x];
        g_base[i] = b;
        g_cursor[i] = b;
    }
}

__global__ void k_fill(const int* __restrict__ src, const int* __restrict__ dst,
                       const float* __restrict__ w, int E) {
    int e = blockIdx.x * blockDim.x + threadIdx.x;
    if (e < E) {
        int pos = atomicAdd(&g_cursor[dst[e]], 1);
        g_epack[pos] = make_int2(src[e], __float_as_int(w[e]));
    }
}

// warp per dst node in [lo,hi): accumulate Tx1 & msum from fp32 xh; write bf16 hi/lo
__global__ void k_gather(int lo, int hi) {
    int wd = lo + ((blockIdx.x * blockDim.x + threadIdx.x) >> 5);
    if (wd >= hi) return;
    int lane = threadIdx.x & 31;
    int cnt = g_hist[wd], base = g_base[wd];
    float disd = g_dis[wd];
    float inv = 1.0f / fmaxf((float)cnt, 1.0f);
    float4 at = make_float4(0.f, 0.f, 0.f, 0.f);
    float4 am = make_float4(0.f, 0.f, 0.f, 0.f);
    int j = 0;
    for (; j + 4 <= cnt; j += 4) {
        int2 e[4];
        float4 v[4];
        float w[4], cn[4];
#pragma unroll
        for (int q = 0; q < 4; q++) e[q] = __ldg(g_epack + base + j + q);
#pragma unroll
        for (int q = 0; q < 4; q++)
            v[q] = __ldg((const float4*)g_xh + (size_t)e[q].x * 32 + lane);
#pragma unroll
        for (int q = 0; q < 4; q++) {
            w[q]  = __int_as_float(e[q].y);
            cn[q] = -g_dis[e[q].x] * w[q] * disd;
        }
#pragma unroll
        for (int q = 0; q < 4; q++) {
            at.x = fmaf(cn[q], v[q].x, at.x); at.y = fmaf(cn[q], v[q].y, at.y);
            at.z = fmaf(cn[q], v[q].z, at.z); at.w = fmaf(cn[q], v[q].w, at.w);
            am.x = fmaf(w[q], v[q].x, am.x);  am.y = fmaf(w[q], v[q].y, am.y);
            am.z = fmaf(w[q], v[q].z, am.z);  am.w = fmaf(w[q], v[q].w, am.w);
        }
    }
    for (; j < cnt; j++) {
        int2 e0 = __ldg(g_epack + base + j);
        float4 v0 = __ldg((const float4*)g_xh + (size_t)e0.x * 32 + lane);
        float w0 = __int_as_float(e0.y);
        float c0 = -g_dis[e0.x] * w0 * disd;
        at.x = fmaf(c0, v0.x, at.x); at.y = fmaf(c0, v0.y, at.y);
        at.z = fmaf(c0, v0.z, at.z); at.w = fmaf(c0, v0.w, at.w);
        am.x = fmaf(w0, v0.x, am.x); am.y = fmaf(w0, v0.y, am.y);
        am.z = fmaf(w0, v0.z, am.z); am.w = fmaf(w0, v0.w, am.w);
    }
    am.x *= inv; am.y *= inv; am.z *= inv; am.w *= inv;
    float ft[4] = {at.x, at.y, at.z, at.w};
    float fm[4] = {am.x, am.y, am.z, am.w};
    __nv_bfloat16 th[4], tl[4], mh[4], ml[4];
#pragma unroll
    for (int q = 0; q < 4; q++) {
        th[q] = __float2bfloat16(ft[q]);
        tl[q] = __float2bfloat16(ft[q] - __bfloat162float(th[q]));
        mh[q] = __float2bfloat16(fm[q]);
        ml[q] = __float2bfloat16(fm[q] - __bfloat162float(mh[q]));
    }
    size_t p = (size_t)wd * D + lane * 4;
    *(uint2*)(g_t1h + p) = make_uint2(pk(th[0], th[1]), pk(th[2], th[3]));
    *(uint2*)(g_t1l + p) = make_uint2(pk(tl[0], tl[1]), pk(tl[2], tl[3]));
    *(uint2*)(g_mnh + p) = make_uint2(pk(mh[0], mh[1]), pk(mh[2], mh[3]));
    *(uint2*)(g_mnl + p) = make_uint2(pk(ml[0], ml[1]), pk(ml[2], ml[3]));
}

// ================= GEMM kernels =================
#define SM_G64 (98304)
#define SM_MID (196608)

// xh = x @ Wp^T + bp ; writes fp32 + bf16 hi/lo ; copies x into 'his'
__global__ __launch_bounds__(256, 2) void k_gemm_xh(const float* __restrict__ x,
                                                    const float* __restrict__ bp,
                                                    float* __restrict__ his, int n) {
    extern __shared__ __align__(256) char sb[];
    int tid = threadIdx.x, wid = tid >> 5, lane = tid & 31;
    int m0 = blockIdx.x * 64;
    int m_base = (wid & 1) * 32, n_base = (wid >> 1) * 32;
    uint32_t base = smem_u32(sb);

    load_async<128>(g_wh[WP], 0, base + 32768, tid);
    load_async<128>(g_wl[WP], 0, base + 65536, tid);
    CPA_COMMIT();
    load_split64_copy(x, m0, n, sb, sb + 16384, his, tid);
    CPA_WAIT0();
    __syncthreads();

    float acc[2][4][4];
#pragma unroll
    for (int a = 0; a < 2; a++)
#pragma unroll
        for (int b = 0; b < 4; b++)
#pragma unroll
            for (int q = 0; q < 4; q++) acc[a][b][q] = 0.f;

    warp_phase32(base, base + 16384, base + 32768, base + 65536, m_base, n_base, lane, acc);

    int rr = lane >> 2, cc = 2 * (lane & 3);
#pragma unroll
    for (int mt = 0; mt < 2; mt++) {
#pragma unroll
        for (int j = 0; j < 4; j++) {
            int col = n_base + j * 8 + cc;
            float b0 = __ldg(bp + col), b1 = __ldg(bp + col + 1);
#pragma unroll
            for (int half = 0; half < 2; half++) {
                int row = m0 + m_base + mt * 16 + rr + half * 8;
                if (row < n) {
                    float va = acc[mt][j][2 * half + 0] + b0;
                    float vb = acc[mt][j][2 * half + 1] + b1;
                    size_t p = (size_t)row * D + col;
                    *(float2*)(g_xh + p) = make_float2(va, vb);
                    __nv_bfloat16 ha = __float2bfloat16(va), hb = __float2bfloat16(vb);
                    __nv_bfloat16 la = __float2bfloat16(va - __bfloat162float(ha));
                    __nv_bfloat16 lb = __float2bfloat16(vb - __bfloat162float(hb));
                    *(uint32_t*)(g_xhh + p) = pk(ha, hb);
                    *(uint32_t*)(g_xhl + p) = pk(la, lb);
                }
            }
        }
    }
}

// mid (256 threads): acc1 = xh@Wc0^T + Tx1@Wc1^T ; acc2 = xh@Wroot^T + mean@Wrel^T
// tiles offset by mtile0 (in 64-row tiles)
__global__ __launch_bounds__(256) void k_gemm_mid(const float* __restrict__ bc,
                                                  const float* __restrict__ brel,
                                                  int mtile0, int n) {
    extern __shared__ __align__(256) char sb[];
    int tid = threadIdx.x, wid = tid >> 5, lane = tid & 31;
    int m0 = (mtile0 + blockIdx.x) * 64;
    int m_base = (wid & 1) * 32, n_base = (wid >> 1) * 32;
    uint32_t base = smem_u32(sb);
    uint32_t a1H = base,          a1L = base + 16384;
    uint32_t a2H = base + 32768,  a2L = base + 49152;
    uint32_t waH = base + 65536,  waL = base + 98304;
    uint32_t wbH = base + 131072, wbL = base + 163840;

    float acc1[2][4][4], acc2[2][4][4];
#pragma unroll
    for (int a = 0; a < 2; a++)
#pragma unroll
        for (int b = 0; b < 4; b++)
#pragma unroll
            for (int q = 0; q < 4; q++) { acc1[a][b][q] = 0.f; acc2[a][b][q] = 0.f; }

    load_async<64>(g_xhh, m0, a1H, tid);
    load_async<64>(g_xhl, m0, a1L, tid);
    load_async<64>(g_t1h, m0, a2H, tid);
    load_async<64>(g_t1l, m0, a2L, tid);
    load_async<128>(g_wh[WC0], 0, waH, tid);
    load_async<128>(g_wl[WC0], 0, waL, tid);
    CPA_COMMIT();
    CPA_WAIT0();
    __syncthreads();

    load_async<128>(g_wh[WC1], 0, wbH, tid);
    load_async<128>(g_wl[WC1], 0, wbL, tid);
    CPA_COMMIT();
    warp_phase32(a1H, a1L, waH, waL, m_base, n_base, lane, acc1);
    CPA_WAIT0();
    __syncthreads();

    load_async<128>(g_wh[WROOT], 0, waH, tid);
    load_async<128>(g_wl[WROOT], 0, waL, tid);
    CPA_COMMIT();
    warp_phase32(a2H, a2L, wbH, wbL, m_base, n_base, lane, acc1);
    CPA_WAIT0();
    __syncthreads();

    load_async<64>(g_mnh, m0, a2H, tid);
    load_async<64>(g_mnl, m0, a2L, tid);
    load_async<128>(g_wh[WREL], 0, wbH, tid);
    load_async<128>(g_wl[WREL], 0, wbL, tid);
    CPA_COMMIT();
    warp_phase32(a1H, a1L, waH, waL, m_base, n_base, lane, acc2);
    CPA_WAIT0();
    __syncthreads();

    warp_phase32(a2H, a2L, wbH, wbL, m_base, n_base, lane, acc2);

    int rr = lane >> 2, cc = 2 * (lane & 3);
#pragma unroll
    for (int mt = 0; mt < 2; mt++) {
#pragma unroll
        for (int j = 0; j < 4; j++) {
            int col = n_base + j * 8 + cc;
            float c0 = __ldg(bc + col),   c1 = __ldg(bc + col + 1);
            float r0 = __ldg(brel + col), r1 = __ldg(brel + col + 1);
#pragma unroll
            for (int half = 0; half < 2; half++) {
                int row = m0 + m_base + mt * 16 + rr + half * 8;
                if (row < n) {
                    float v1a = acc1[mt][j][2 * half + 0] + c0;
                    float v1b = acc1[mt][j][2 * half + 1] + c1;
                    float v2a = acc2[mt][j][2 * half + 0] + r0;
                    float v2b = acc2[mt][j][2 * half + 1] + r1;
                    v1a = v1a >= 0.f ? v1a : 0.01f * v1a;
                    v1b = v1b >= 0.f ? v1b : 0.01f * v1b;
                    v2a = v2a >= 0.f ? v2a : 0.01f * v2a;
                    v2b = v2b >= 0.f ? v2b : 0.01f * v2b;
                    float oa = v1a + v2a, ob = v1b + v2b;
                    __nv_bfloat16 ha = __float2bfloat16(oa), hb = __float2bfloat16(ob);
                    __nv_bfloat16 la = __float2bfloat16(oa - __bfloat162float(ha));
                    __nv_bfloat16 lb = __float2bfloat16(ob - __bfloat162float(hb));
                    size_t p = (size_t)row * D + col;
                    *(uint32_t*)(g_o12h + p) = pk(ha, hb);
                    *(uint32_t*)(g_o12l + p) = pk(la, lb);
                }
            }
        }
    }
}

// o3 = o12 @ Wl^T + bl -> fp32 ; tiles offset by mtile0
__global__ __launch_bounds__(256, 2) void k_gemm_fin(const float* __restrict__ bl,
                                                     float* __restrict__ out2,
                                                     int mtile0, int n) {
    extern __shared__ __align__(256) char sb[];
    int tid = threadIdx.x, wid = tid >> 5, lane = tid & 31;
    int m0 = (mtile0 + blockIdx.x) * 64;
    int m_base = (wid & 1) * 32, n_base = (wid >> 1) * 32;
    uint32_t base = smem_u32(sb);

    load_async<64>(g_o12h, m0, base, tid);
    load_async<64>(g_o12l, m0, base + 16384, tid);
    load_async<128>(g_wh[WLIN], 0, base + 32768, tid);
    load_async<128>(g_wl[WLIN], 0, base + 65536, tid);
    CPA_COMMIT();
    CPA_WAIT0();
    __syncthreads();

    float acc[2][4][4];
#pragma unroll
    for (int a = 0; a < 2; a++)
#pragma unroll
        for (int b = 0; b < 4; b++)
#pragma unroll
            for (int q = 0; q < 4; q++) acc[a][b][q] = 0.f;

    warp_phase32(base, base + 16384, base + 32768, base + 65536, m_base, n_base, lane, acc);

    int rr = lane >> 2, cc = 2 * (lane & 3);
#pragma unroll
    for (int mt = 0; mt < 2; mt++) {
#pragma unroll
        for (int j = 0; j < 4; j++) {
            int col = n_base + j * 8 + cc;
            float b0 = __ldg(bl + col), b1 = __ldg(bl + col + 1);
#pragma unroll
            for (int half = 0; half < 2; half++) {
                int row = m0 + m_base + mt * 16 + rr + half * 8;
                if (row < n)
                    *(float2*)(out2 + (size_t)row * D + col) =
                        make_float2(acc[mt][j][2 * half + 0] + b0,
                                    acc[mt][j][2 * half + 1] + b1);
            }
        }
    }
}

// ================= launch =================
extern "C" void kernel_launch(void* const* d_in, const int* in_sizes, int n_in,
                              void* d_out, int out_size) {
    const float* x     = (const float*)d_in[1];
    const int*   ei    = (const int*)  d_in[2];
    const float* ew    = (const float*)d_in[3];
    const float* Wp    = (const float*)d_in[4];
    const float* bp    = (const float*)d_in[5];
    const float* Wc0   = (const float*)d_in[6];
    const float* Wc1   = (const float*)d_in[7];
    const float* bc    = (const float*)d_in[8];
    const float* Wrel  = (const float*)d_in[9];
    const float* brel  = (const float*)d_in[10];
    const float* Wroot = (const float*)d_in[11];
    const float* Wl    = (const float*)d_in[12];
    const float* bl    = (const float*)d_in[13];

    int n = in_sizes[1] / D;
    int E = in_sizes[3];
    float* out = (float*)d_out;
    float* out2 = out + (size_t)n * D;

    cudaFuncSetAttribute(k_gemm_xh,  cudaFuncAttributeMaxDynamicSharedMemorySize, SM_G64);
    cudaFuncSetAttribute(k_gemm_mid, cudaFuncAttributeMaxDynamicSharedMemorySize, SM_MID);
    cudaFuncSetAttribute(k_gemm_fin, cudaFuncAttributeMaxDynamicSharedMemorySize, SM_G64);

    int g64 = (n + 63) / 64;
    int gA = (g64 + 1) / 2;          // 50/50 split (validated in R12)
    int gB = g64 - gA;
    int h  = gA * 64;
    if (h > n) h = n;
    int nscan = (n + 1023) / 1024;   // scan blocks (<= 64)

    cudaStream_t s2;
    cudaStreamCreateWithFlags(&s2, cudaStreamNonBlocking);
    cudaEvent_t e1, e_xh, e_gA, e_done;
    cudaEventCreateWithFlags(&e1,    cudaEventDisableTiming);
    cudaEventCreateWithFlags(&e_xh,  cudaEventDisableTiming);
    cudaEventCreateWithFlags(&e_gA,  cudaEventDisableTiming);
    cudaEventCreateWithFlags(&e_done,cudaEventDisableTiming);

    cudaEventRecord(e1, 0);
    cudaStreamWaitEvent(s2, e1, 0);

    // stream 0: graph preprocessing (parallel hierarchical scan)
    k_zero_small<<<(n + 255) / 256, 256>>>(n);
    k_hist<<<(E + 255) / 256, 256>>>(ei, ei + E, ew, E);
    k_scan_local<<<nscan, 1024>>>(n);
    k_scan_bsum<<<1, 64>>>(nscan);
    k_scan_add<<<nscan, 1024>>>(n);
    k_fill<<<(E + 255) / 256, 256>>>(ei, ei + E, ew, E);

    // stream s2: weights + first GEMM
    k_split_w<<<dim3(64, 6), 256, 0, s2>>>(Wp, Wc0, Wc1, Wrel, Wroot, Wl);
    k_gemm_xh<<<g64, 256, SM_G64, s2>>>(x, bp, out, n);
    cudaEventRecord(e_xh, s2);

    // stream 0: gather half A (needs full xh + fill)
    cudaStreamWaitEvent(0, e_xh, 0);
    k_gather<<<(h * 32 + 255) / 256, 256>>>(0, h);
    cudaEventRecord(e_gA, 0);

    // stream 0 continues: gather half B, then mid/fin for half B
    if (n > h) k_gather<<<((n - h) * 32 + 255) / 256, 256>>>(h, n);
    if (gB > 0) {
        k_gemm_mid<<<gB, 256, SM_MID>>>(bc, brel, gA, n);
        k_gemm_fin<<<gB, 256, SM_G64>>>(bl, out2, gA, n);
    }

    // stream s2: mid/fin for half A (overlaps gather B / mid B on stream 0)
    cudaStreamWaitEvent(s2, e_gA, 0);
    k_gemm_mid<<<gA, 256, SM_MID, s2>>>(bc, brel, 0, n);
    k_gemm_fin<<<gA, 256, SM_G64, s2>>>(bl, out2, 0, n);
    cudaEventRecord(e_done, s2);

    // join
    cudaStreamWaitEvent(0, e_done, 0);

    cudaStreamDestroy(s2);
    cudaEventDestroy(e1);
    cudaEventDestroy(e_xh);
    cudaEventDestroy(e_gA);
    cudaEventDestroy(e_done);
}

// round 17
// speedup vs baseline: 1.4593x; 1.0182x over previous
#include <cuda_runtime.h>
#include <cuda_bf16.h>
#include <cstdint>
#include <cstddef>

#define D 128
#define MAXN 50176
#define MAXE 1048576

// ================= global scratch (no allocations allowed) =================
__device__ __align__(16) float g_xh  [(size_t)MAXN * D];           // fp32 xh (gather source)
__device__ __align__(16) __nv_bfloat16 g_xhh[(size_t)MAXN * D];    // xh hi
__device__ __align__(16) __nv_bfloat16 g_xhl[(size_t)MAXN * D];    // xh lo
__device__ __align__(16) __nv_bfloat16 g_t1h[(size_t)MAXN * D];    // Tx1 hi
__device__ __align__(16) __nv_bfloat16 g_t1l[(size_t)MAXN * D];    // Tx1 lo
__device__ __align__(16) __nv_bfloat16 g_mnh[(size_t)MAXN * D];    // mean hi
__device__ __align__(16) __nv_bfloat16 g_mnl[(size_t)MAXN * D];    // mean lo
__device__ __align__(16) __nv_bfloat16 g_o12h[(size_t)MAXN * D];
__device__ __align__(16) __nv_bfloat16 g_o12l[(size_t)MAXN * D];
__device__ __align__(16) __nv_bfloat16 g_wh[6][D * D];
__device__ __align__(16) __nv_bfloat16 g_wl[6][D * D];
__device__ float g_deg [MAXN];
__device__ float g_dis [MAXN];
__device__ int   g_hist[MAXN];
__device__ int   g_base[MAXN];
__device__ int   g_cursor[MAXN];
__device__ int   g_bsum[64];
__device__ __align__(16) int2 g_epack[MAXE];

enum { WP = 0, WC0, WC1, WREL, WROOT, WLIN };

// ================= helpers =================
__device__ __forceinline__ uint32_t smem_u32(const void* p) {
    return (uint32_t)__cvta_generic_to_shared(p);
}
__device__ __forceinline__ uint32_t sw_off(int row, int c16) {
    return (uint32_t)(row * 256 + ((c16 ^ (row & 7)) << 4));
}
__device__ __forceinline__ void ldx4(uint32_t r[4], uint32_t a) {
    asm volatile("ldmatrix.sync.aligned.m8n8.x4.shared.b16 {%0,%1,%2,%3}, [%4];"
                 : "=r"(r[0]), "=r"(r[1]), "=r"(r[2]), "=r"(r[3]) : "r"(a));
}
__device__ __forceinline__ void mma16816(float c[4], const uint32_t a[4],
                                         uint32_t b0, uint32_t b1) {
    asm volatile("mma.sync.aligned.m16n8k16.row.col.f32.bf16.bf16.f32 "
                 "{%0,%1,%2,%3}, {%4,%5,%6,%7}, {%8,%9}, {%0,%1,%2,%3};"
                 : "+f"(c[0]), "+f"(c[1]), "+f"(c[2]), "+f"(c[3])
                 : "r"(a[0]), "r"(a[1]), "r"(a[2]), "r"(a[3]), "r"(b0), "r"(b1));
}
__device__ __forceinline__ uint32_t pk(__nv_bfloat16 a, __nv_bfloat16 b) {
    return (uint32_t)__bfloat16_as_ushort(a) | ((uint32_t)__bfloat16_as_ushort(b) << 16);
}
__device__ __forceinline__ void cpa16(uint32_t dst, const void* src) {
    asm volatile("cp.async.cg.shared.global [%0], [%1], 16;" :: "r"(dst), "l"(src));
}
#define CPA_COMMIT() asm volatile("cp.async.commit_group;" ::: "memory")
#define CPA_WAIT0()  asm volatile("cp.async.wait_group 0;" ::: "memory")

template<int ROWS>
__device__ __forceinline__ void load_async(const __nv_bfloat16* __restrict__ src, int m0,
                                           uint32_t dst, int tid) {
#pragma unroll
    for (int t = 0; t < ROWS * 16 / 256; t++) {
        int idx = tid + t * 256;
        int row = idx >> 4, c16 = idx & 15;
        cpa16(dst + sw_off(row, c16), src + (size_t)(m0 + row) * D + c16 * 8);
    }
}

// load 64x128 fp32 tile (row guard), split hi/lo swizzled; also copy rows to 'his'
__device__ __forceinline__ void load_split64_copy(const float* __restrict__ src, int m0, int n,
                                                  char* ah, char* al,
                                                  float* __restrict__ his, int tid) {
#pragma unroll
    for (int t = 0; t < 4; t++) {
        int idx = tid + t * 256;
        int row = idx >> 4, c16 = idx & 15;
        int gr = m0 + row;
        float4 v0 = make_float4(0.f, 0.f, 0.f, 0.f), v1 = v0;
        if (gr < n) {
            const float* p = src + (size_t)gr * D + c16 * 8;
            v0 = *(const float4*)p;
            v1 = *(const float4*)(p + 4);
            float* q = his + (size_t)gr * D + c16 * 8;
            *(float4*)q = v0;
            *(float4*)(q + 4) = v1;
        }
        float f[8] = {v0.x, v0.y, v0.z, v0.w, v1.x, v1.y, v1.z, v1.w};
        __nv_bfloat16 h[8], l[8];
#pragma unroll
        for (int q = 0; q < 8; q++) {
            h[q] = __float2bfloat16(f[q]);
            l[q] = __float2bfloat16(f[q] - __bfloat162float(h[q]));
        }
        uint32_t off = sw_off(row, c16);
        *(uint4*)(ah + off) = make_uint4(pk(h[0],h[1]), pk(h[2],h[3]), pk(h[4],h[5]), pk(h[6],h[7]));
        *(uint4*)(al + off) = make_uint4(pk(l[0],l[1]), pk(l[2],l[3]), pk(l[4],l[5]), pk(l[6],l[7]));
    }
}

// warp tile 32(m) x 32(n), K=128; acc += Ah*Bh + Ah*Bl + Al*Bh
__device__ __forceinline__ void warp_phase32(
    uint32_t aH, uint32_t aL, uint32_t bH, uint32_t bL,
    int m_base, int n_base, int lane, float acc[2][4][4])
{
    int r = lane & 15, chs = lane >> 4;
#pragma unroll
    for (int kk = 0; kk < 8; kk++) {
        int c = 2 * kk + chs;
        uint32_t ah[2][4], al[2][4], bh[2][4], bl[2][4];
#pragma unroll
        for (int mt = 0; mt < 2; mt++) {
            uint32_t off = sw_off(m_base + mt * 16 + r, c);
            ldx4(ah[mt], aH + off);
            ldx4(al[mt], aL + off);
        }
#pragma unroll
        for (int g = 0; g < 2; g++) {
            uint32_t off = sw_off(n_base + g * 16 + r, c);
            ldx4(bh[g], bH + off);
            ldx4(bl[g], bL + off);
        }
#pragma unroll
        for (int mt = 0; mt < 2; mt++)
#pragma unroll
            for (int j = 0; j < 4; j++) {
                int g = j >> 1, p = j & 1;
                mma16816(acc[mt][j], ah[mt], bh[g][p], bh[g][p + 2]);
                mma16816(acc[mt][j], ah[mt], bl[g][p], bl[g][p + 2]);
                mma16816(acc[mt][j], al[mt], bh[g][p], bh[g][p + 2]);
            }
    }
}

// ================= preprocessing =================
__global__ void k_split_w(const float* w0, const float* w1, const float* w2,
                          const float* w3, const float* w4, const float* w5) {
    const float* srcs[6] = {w0, w1, w2, w3, w4, w5};
    int ws = blockIdx.y;
    int i = blockIdx.x * 256 + threadIdx.x;
    float v = srcs[ws][i];
    __nv_bfloat16 h = __float2bfloat16(v);
    g_wh[ws][i] = h;
    g_wl[ws][i] = __float2bfloat16(v - __bfloat162float(h));
}

__global__ void k_zero_small(int n) {
    int i = blockIdx.x * blockDim.x + threadIdx.x;
    if (i < n) { g_deg[i] = 0.f; g_hist[i] = 0; }
}

// 2 edges per thread for MLP (latency-bound atomics)
__global__ void k_hist(const int* __restrict__ src, const int* __restrict__ dst,
                       const float* __restrict__ w, int E) {
    int e0 = (blockIdx.x * blockDim.x + threadIdx.x) * 2;
    int e1 = e0 + 1;
    if (e0 >= E) return;
    int s0 = __ldg(src + e0), d0 = __ldg(dst + e0);
    float w0 = __ldg(w + e0);
    bool has1 = e1 < E;
    int s1 = 0, d1 = 0; float w1 = 0.f;
    if (has1) { s1 = __ldg(src + e1); d1 = __ldg(dst + e1); w1 = __ldg(w + e1); }
    atomicAdd(&g_deg[s0], w0);
    atomicAdd(&g_hist[d0], 1);
    if (has1) {
        atomicAdd(&g_deg[s1], w1);
        atomicAdd(&g_hist[d1], 1);
    }
}

// hierarchical scan stage A: per-block local exclusive scan of g_hist -> g_base,
// block total -> g_bsum ; also dis = rsqrt(deg)
__global__ __launch_bounds__(1024) void k_scan_local(int n) {
    __shared__ int buf[32];
    int tid = threadIdx.x, lane = tid & 31, wid = tid >> 5;
    int i = blockIdx.x * 1024 + tid;
    int v = 0;
    if (i < n) {
        v = g_hist[i];
        float d = g_deg[i];
        g_dis[i] = d > 0.f ? rsqrtf(d) : 0.f;
    }
    int x = v;
#pragma unroll
    for (int o = 1; o < 32; o <<= 1) {
        int y = __shfl_up_sync(~0u, x, o);
        if (lane >= o) x += y;
    }
    if (lane == 31) buf[wid] = x;
    __syncthreads();
    if (wid == 0) {
        int s = buf[lane];
#pragma unroll
        for (int o = 1; o < 32; o <<= 1) {
            int y = __shfl_up_sync(~0u, s, o);
            if (lane >= o) s += y;
        }
        buf[lane] = s;
    }
    __syncthreads();
    int incl = x + (wid > 0 ? buf[wid - 1] : 0);
    if (i < n) g_base[i] = incl - v;           // local exclusive
    if (tid == 0) g_bsum[blockIdx.x] = buf[31]; // block total
}

// stage B: exclusive scan of block sums (nb <= 64, 2 warps)
__global__ void k_scan_bsum(int nb) {
    __shared__ int wtot[2];
    int t = threadIdx.x, lane = t & 31, w = t >> 5;
    int v = (t < nb) ? g_bsum[t] : 0;
    int x = v;
#pragma unroll
    for (int o = 1; o < 32; o <<= 1) {
        int y = __shfl_up_sync(~0u, x, o);
        if (lane >= o) x += y;
    }
    if (lane == 31) wtot[w] = x;
    __syncthreads();
    int add = (w == 1) ? wtot[0] : 0;
    if (t < nb) g_bsum[t] = x - v + add;       // exclusive
}

// stage C: add block offsets, produce base + cursor
__global__ __launch_bounds__(1024) void k_scan_add(int n) {
    int i = blockIdx.x * 1024 + threadIdx.x;
    if (i < n) {
        int b = g_base[i] + g_bsum[blockIdx.x];
        g_base[i] = b;
        g_cursor[i] = b;
    }
}

// 2 edges per thread for MLP
__global__ void k_fill(const int* __restrict__ src, const int* __restrict__ dst,
                       const float* __restrict__ w, int E) {
    int e0 = (blockIdx.x * blockDim.x + threadIdx.x) * 2;
    int e1 = e0 + 1;
    if (e0 >= E) return;
    int s0 = __ldg(src + e0), d0 = __ldg(dst + e0);
    float w0 = __ldg(w + e0);
    bool has1 = e1 < E;
    int s1 = 0, d1 = 0; float w1 = 0.f;
    if (has1) { s1 = __ldg(src + e1); d1 = __ldg(dst + e1); w1 = __ldg(w + e1); }
    int p0 = atomicAdd(&g_cursor[d0], 1);
    g_epack[p0] = make_int2(s0, __float_as_int(w0));
    if (has1) {
        int p1 = atomicAdd(&g_cursor[d1], 1);
        g_epack[p1] = make_int2(s1, __float_as_int(w1));
    }
}

// warp per dst node in [lo,hi): accumulate Tx1 & msum from fp32 xh; write bf16 hi/lo
__global__ void k_gather(int lo, int hi) {
    int wd = lo + ((blockIdx.x * blockDim.x + threadIdx.x) >> 5);
    if (wd >= hi) return;
    int lane = threadIdx.x & 31;
    int cnt = g_hist[wd], base = g_base[wd];
    float disd = g_dis[wd];
    float inv = 1.0f / fmaxf((float)cnt, 1.0f);
    float4 at = make_float4(0.f, 0.f, 0.f, 0.f);
    float4 am = make_float4(0.f, 0.f, 0.f, 0.f);
    int j = 0;
    for (; j + 4 <= cnt; j += 4) {
        int2 e[4];
        float4 v[4];
        float w[4], cn[4];
#pragma unroll
        for (int q = 0; q < 4; q++) e[q] = __ldg(g_epack + base + j + q);
#pragma unroll
        for (int q = 0; q < 4; q++)
            v[q] = __ldg((const float4*)g_xh + (size_t)e[q].x * 32 + lane);
#pragma unroll
        for (int q = 0; q < 4; q++) {
            w[q]  = __int_as_float(e[q].y);
            cn[q] = -g_dis[e[q].x] * w[q] * disd;
        }
#pragma unroll
        for (int q = 0; q < 4; q++) {
            at.x = fmaf(cn[q], v[q].x, at.x); at.y = fmaf(cn[q], v[q].y, at.y);
            at.z = fmaf(cn[q], v[q].z, at.z); at.w = fmaf(cn[q], v[q].w, at.w);
            am.x = fmaf(w[q], v[q].x, am.x);  am.y = fmaf(w[q], v[q].y, am.y);
            am.z = fmaf(w[q], v[q].z, am.z);  am.w = fmaf(w[q], v[q].w, am.w);
        }
    }
    for (; j < cnt; j++) {
        int2 e0 = __ldg(g_epack + base + j);
        float4 v0 = __ldg((const float4*)g_xh + (size_t)e0.x * 32 + lane);
        float w0 = __int_as_float(e0.y);
        float c0 = -g_dis[e0.x] * w0 * disd;
        at.x = fmaf(c0, v0.x, at.x); at.y = fmaf(c0, v0.y, at.y);
        at.z = fmaf(c0, v0.z, at.z); at.w = fmaf(c0, v0.w, at.w);
        am.x = fmaf(w0, v0.x, am.x); am.y = fmaf(w0, v0.y, am.y);
        am.z = fmaf(w0, v0.z, am.z); am.w = fmaf(w0, v0.w, am.w);
    }
    am.x *= inv; am.y *= inv; am.z *= inv; am.w *= inv;
    float ft[4] = {at.x, at.y, at.z, at.w};
    float fm[4] = {am.x, am.y, am.z, am.w};
    __nv_bfloat16 th[4], tl[4], mh[4], ml[4];
#pragma unroll
    for (int q = 0; q < 4; q++) {
        th[q] = __float2bfloat16(ft[q]);
        tl[q] = __float2bfloat16(ft[q] - __bfloat162float(th[q]));
        mh[q] = __float2bfloat16(fm[q]);
        ml[q] = __float2bfloat16(fm[q] - __bfloat162float(mh[q]));
    }
    size_t p = (size_t)wd * D + lane * 4;
    *(uint2*)(g_t1h + p) = make_uint2(pk(th[0], th[1]), pk(th[2], th[3]));
    *(uint2*)(g_t1l + p) = make_uint2(pk(tl[0], tl[1]), pk(tl[2], tl[3]));
    *(uint2*)(g_mnh + p) = make_uint2(pk(mh[0], mh[1]), pk(mh[2], mh[3]));
    *(uint2*)(g_mnl + p) = make_uint2(pk(ml[0], ml[1]), pk(ml[2], ml[3]));
}

// ================= GEMM kernels =================
#define SM_G64 (98304)
#define SM_MID (196608)

// xh = x @ Wp^T + bp ; writes fp32 + bf16 hi/lo ; copies x into 'his'
__global__ __launch_bounds__(256, 2) void k_gemm_xh(const float* __restrict__ x,
                                                    const float* __restrict__ bp,
                                                    float* __restrict__ his, int n) {
    extern __shared__ __align__(256) char sb[];
    int tid = threadIdx.x, wid = tid >> 5, lane = tid & 31;
    int m0 = blockIdx.x * 64;
    int m_base = (wid & 1) * 32, n_base = (wid >> 1) * 32;
    uint32_t base = smem_u32(sb);

    load_async<128>(g_wh[WP], 0, base + 32768, tid);
    load_async<128>(g_wl[WP], 0, base + 65536, tid);
    CPA_COMMIT();
    load_split64_copy(x, m0, n, sb, sb + 16384, his, tid);
    CPA_WAIT0();
    __syncthreads();

    float acc[2][4][4];
#pragma unroll
    for (int a = 0; a < 2; a++)
#pragma unroll
        for (int b = 0; b < 4; b++)
#pragma unroll
            for (int q = 0; q < 4; q++) acc[a][b][q] = 0.f;

    warp_phase32(base, base + 16384, base + 32768, base + 65536, m_base, n_base, lane, acc);

    int rr = lane >> 2, cc = 2 * (lane & 3);
#pragma unroll
    for (int mt = 0; mt < 2; mt++) {
#pragma unroll
        for (int j = 0; j < 4; j++) {
            int col = n_base + j * 8 + cc;
            float b0 = __ldg(bp + col), b1 = __ldg(bp + col + 1);
#pragma unroll
            for (int half = 0; half < 2; half++) {
                int row = m0 + m_base + mt * 16 + rr + half * 8;
                if (row < n) {
                    float va = acc[mt][j][2 * half + 0] + b0;
                    float vb = acc[mt][j][2 * half + 1] + b1;
                    size_t p = (size_t)row * D + col;
                    *(float2*)(g_xh + p) = make_float2(va, vb);
                    __nv_bfloat16 ha = __float2bfloat16(va), hb = __float2bfloat16(vb);
                    __nv_bfloat16 la = __float2bfloat16(va - __bfloat162float(ha));
                    __nv_bfloat16 lb = __float2bfloat16(vb - __bfloat162float(hb));
                    *(uint32_t*)(g_xhh + p) = pk(ha, hb);
                    *(uint32_t*)(g_xhl + p) = pk(la, lb);
                }
            }
        }
    }
}

// mid (256 threads): acc1 = xh@Wc0^T + Tx1@Wc1^T ; acc2 = xh@Wroot^T + mean@Wrel^T
// tiles offset by mtile0 (in 64-row tiles)
__global__ __launch_bounds__(256) void k_gemm_mid(const float* __restrict__ bc,
                                                  const float* __restrict__ brel,
                                                  int mtile0, int n) {
    extern __shared__ __align__(256) char sb[];
    int tid = threadIdx.x, wid = tid >> 5, lane = tid & 31;
    int m0 = (mtile0 + blockIdx.x) * 64;
    int m_base = (wid & 1) * 32, n_base = (wid >> 1) * 32;
    uint32_t base = smem_u32(sb);
    uint32_t a1H = base,          a1L = base + 16384;
    uint32_t a2H = base + 32768,  a2L = base + 49152;
    uint32_t waH = base + 65536,  waL = base + 98304;
    uint32_t wbH = base + 131072, wbL = base + 163840;

    float acc1[2][4][4], acc2[2][4][4];
#pragma unroll
    for (int a = 0; a < 2; a++)
#pragma unroll
        for (int b = 0; b < 4; b++)
#pragma unroll
            for (int q = 0; q < 4; q++) { acc1[a][b][q] = 0.f; acc2[a][b][q] = 0.f; }

    load_async<64>(g_xhh, m0, a1H, tid);
    load_async<64>(g_xhl, m0, a1L, tid);
    load_async<64>(g_t1h, m0, a2H, tid);
    load_async<64>(g_t1l, m0, a2L, tid);
    load_async<128>(g_wh[WC0], 0, waH, tid);
    load_async<128>(g_wl[WC0], 0, waL, tid);
    CPA_COMMIT();
    CPA_WAIT0();
    __syncthreads();

    load_async<128>(g_wh[WC1], 0, wbH, tid);
    load_async<128>(g_wl[WC1], 0, wbL, tid);
    CPA_COMMIT();
    warp_phase32(a1H, a1L, waH, waL, m_base, n_base, lane, acc1);
    CPA_WAIT0();
    __syncthreads();

    load_async<128>(g_wh[WROOT], 0, waH, tid);
    load_async<128>(g_wl[WROOT], 0, waL, tid);
    CPA_COMMIT();
    warp_phase32(a2H, a2L, wbH, wbL, m_base, n_base, lane, acc1);
    CPA_WAIT0();
    __syncthreads();

    load_async<64>(g_mnh, m0, a2H, tid);
    load_async<64>(g_mnl, m0, a2L, tid);
    load_async<128>(g_wh[WREL], 0, wbH, tid);
    load_async<128>(g_wl[WREL], 0, wbL, tid);
    CPA_COMMIT();
    warp_phase32(a1H, a1L, waH, waL, m_base, n_base, lane, acc2);
    CPA_WAIT0();
    __syncthreads();

    warp_phase32(a2H, a2L, wbH, wbL, m_base, n_base, lane, acc2);

    int rr = lane >> 2, cc = 2 * (lane & 3);
#pragma unroll
    for (int mt = 0; mt < 2; mt++) {
#pragma unroll
        for (int j = 0; j < 4; j++) {
            int col = n_base + j * 8 + cc;
            float c0 = __ldg(bc + col),   c1 = __ldg(bc + col + 1);
            float r0 = __ldg(brel + col), r1 = __ldg(brel + col + 1);
#pragma unroll
            for (int half = 0; half < 2; half++) {
                int row = m0 + m_base + mt * 16 + rr + half * 8;
                if (row < n) {
                    float v1a = acc1[mt][j][2 * half + 0] + c0;
                    float v1b = acc1[mt][j][2 * half + 1] + c1;
                    float v2a = acc2[mt][j][2 * half + 0] + r0;
                    float v2b = acc2[mt][j][2 * half + 1] + r1;
                    v1a = v1a >= 0.f ? v1a : 0.01f * v1a;
                    v1b = v1b >= 0.f ? v1b : 0.01f * v1b;
                    v2a = v2a >= 0.f ? v2a : 0.01f * v2a;
                    v2b = v2b >= 0.f ? v2b : 0.01f * v2b;
                    float oa = v1a + v2a, ob = v1b + v2b;
                    __nv_bfloat16 ha = __float2bfloat16(oa), hb = __float2bfloat16(ob);
                    __nv_bfloat16 la = __float2bfloat16(oa - __bfloat162float(ha));
                    __nv_bfloat16 lb = __float2bfloat16(ob - __bfloat162float(hb));
                    size_t p = (size_t)row * D + col;
                    *(uint32_t*)(g_o12h + p) = pk(ha, hb);
                    *(uint32_t*)(g_o12l + p) = pk(la, lb);
                }
            }
        }
    }
}

// o3 = o12 @ Wl^T + bl -> fp32 ; tiles offset by mtile0
__global__ __launch_bounds__(256, 2) void k_gemm_fin(const float* __restrict__ bl,
                                                     float* __restrict__ out2,
                                                     int mtile0, int n) {
    extern __shared__ __align__(256) char sb[];
    int tid = threadIdx.x, wid = tid >> 5, lane = tid & 31;
    int m0 = (mtile0 + blockIdx.x) * 64;
    int m_base = (wid & 1) * 32, n_base = (wid >> 1) * 32;
    uint32_t base = smem_u32(sb);

    load_async<64>(g_o12h, m0, base, tid);
    load_async<64>(g_o12l, m0, base + 16384, tid);
    load_async<128>(g_wh[WLIN], 0, base + 32768, tid);
    load_async<128>(g_wl[WLIN], 0, base + 65536, tid);
    CPA_COMMIT();
    CPA_WAIT0();
    __syncthreads();

    float acc[2][4][4];
#pragma unroll
    for (int a = 0; a < 2; a++)
#pragma unroll
        for (int b = 0; b < 4; b++)
#pragma unroll
            for (int q = 0; q < 4; q++) acc[a][b][q] = 0.f;

    warp_phase32(base, base + 16384, base + 32768, base + 65536, m_base, n_base, lane, acc);

    int rr = lane >> 2, cc = 2 * (lane & 3);
#pragma unroll
    for (int mt = 0; mt < 2; mt++) {
#pragma unroll
        for (int j = 0; j < 4; j++) {
            int col = n_base + j * 8 + cc;
            float b0 = __ldg(bl + col), b1 = __ldg(bl + col + 1);
#pragma unroll
            for (int half = 0; half < 2; half++) {
                int row = m0 + m_base + mt * 16 + rr + half * 8;
                if (row < n)
                    *(float2*)(out2 + (size_t)row * D + col) =
                        make_float2(acc[mt][j][2 * half + 0] + b0,
                                    acc[mt][j][2 * half + 1] + b1);
            }
        }
    }
}

// ================= launch =================
extern "C" void kernel_launch(void* const* d_in, const int* in_sizes, int n_in,
                              void* d_out, int out_size) {
    const float* x     = (const float*)d_in[1];
    const int*   ei    = (const int*)  d_in[2];
    const float* ew    = (const float*)d_in[3];
    const float* Wp    = (const float*)d_in[4];
    const float* bp    = (const float*)d_in[5];
    const float* Wc0   = (const float*)d_in[6];
    const float* Wc1   = (const float*)d_in[7];
    const float* bc    = (const float*)d_in[8];
    const float* Wrel  = (const float*)d_in[9];
    const float* brel  = (const float*)d_in[10];
    const float* Wroot = (const float*)d_in[11];
    const float* Wl    = (const float*)d_in[12];
    const float* bl    = (const float*)d_in[13];

    int n = in_sizes[1] / D;
    int E = in_sizes[3];
    float* out = (float*)d_out;
    float* out2 = out + (size_t)n * D;

    cudaFuncSetAttribute(k_gemm_xh,  cudaFuncAttributeMaxDynamicSharedMemorySize, SM_G64);
    cudaFuncSetAttribute(k_gemm_mid, cudaFuncAttributeMaxDynamicSharedMemorySize, SM_MID);
    cudaFuncSetAttribute(k_gemm_fin, cudaFuncAttributeMaxDynamicSharedMemorySize, SM_G64);

    int g64 = (n + 63) / 64;
    int gA = (g64 + 1) / 2;          // 50/50 split (validated in R12)
    int gB = g64 - gA;
    int h  = gA * 64;
    if (h > n) h = n;
    int nscan = (n + 1023) / 1024;   // scan blocks (<= 64)
    int epairs = (E + 1) / 2;

    cudaStream_t s2;
    cudaStreamCreateWithFlags(&s2, cudaStreamNonBlocking);
    cudaEvent_t e1, e_xh, e_gA, e_done;
    cudaEventCreateWithFlags(&e1,    cudaEventDisableTiming);
    cudaEventCreateWithFlags(&e_xh,  cudaEventDisableTiming);
    cudaEventCreateWithFlags(&e_gA,  cudaEventDisableTiming);
    cudaEventCreateWithFlags(&e_done,cudaEventDisableTiming);

    cudaEventRecord(e1, 0);
    cudaStreamWaitEvent(s2, e1, 0);

    // stream 0: graph preprocessing (parallel hierarchical scan)
    k_zero_small<<<(n + 255) / 256, 256>>>(n);
    k_hist<<<(epairs + 255) / 256, 256>>>(ei, ei + E, ew, E);
    k_scan_local<<<nscan, 1024>>>(n);
    k_scan_bsum<<<1, 64>>>(nscan);
    k_scan_add<<<nscan, 1024>>>(n);
    k_fill<<<(epairs + 255) / 256, 256>>>(ei, ei + E, ew, E);

    // stream s2: weights + first GEMM
    k_split_w<<<dim3(64, 6), 256, 0, s2>>>(Wp, Wc0, Wc1, Wrel, Wroot, Wl);
    k_gemm_xh<<<g64, 256, SM_G64, s2>>>(x, bp, out, n);
    cudaEventRecord(e_xh, s2);

    // stream 0: gather half A (needs full xh + fill)
    cudaStreamWaitEvent(0, e_xh, 0);
    k_gather<<<(h * 32 + 255) / 256, 256>>>(0, h);
    cudaEventRecord(e_gA, 0);

    // stream 0 continues: gather half B, then mid/fin for half B
    if (n > h) k_gather<<<((n - h) * 32 + 255) / 256, 256>>>(h, n);
    if (gB > 0) {
        k_gemm_mid<<<gB, 256, SM_MID>>>(bc, brel, gA, n);
        k_gemm_fin<<<gB, 256, SM_G64>>>(bl, out2, gA, n);
    }

    // stream s2: mid/fin for half A (overlaps gather B / mid B on stream 0)
    cudaStreamWaitEvent(s2, e_gA, 0);
    k_gemm_mid<<<gA, 256, SM_MID, s2>>>(bc, brel, 0, n);
    k_gemm_fin<<<gA, 256, SM_G64, s2>>>(bl, out2, 0, n);
    cudaEventRecord(e_done, s2);

    // join
    cudaStreamWaitEvent(0, e_done, 0);

    cudaStreamDestroy(s2);
    cudaEventDestroy(e1);
    cudaEventDestroy(e_xh);
    cudaEventDestroy(e_gA);
    cudaEventDestroy(e_done);
}